// round 12
// baseline (speedup 1.0000x reference)
#include <cuda_runtime.h>
#include <math_constants.h>

// Problem constants (fixed by the dataset)
#define NN   20000      // nodes
#define EE   640000     // edges
#define HCC  128        // H * C
#define NH   4          // heads
#define CH   32         // channels per head
#define DOUT 64
#define CAP  128        // per-dst bucket capacity (Poisson(32): P(deg>=128) ~ 1e-40)

// ---------------- device scratch (static: no allocations allowed) -----------
__device__ float g_XL[NN * HCC];
__device__ float g_XR[NN * HCC];
__device__ float g_H [NN * HCC];
__device__ int   g_cnt[NN];          // per-dst degree (bucket fill counter)
__device__ float g_asum[NN];         // sum of non-self incoming edge_attr
__device__ int   g_ascnt[NN];        // count of non-self incoming edges
__device__ int2  g_ecsr[NN * CAP];   // bucketed (src, edge_attr bits) per dst

// ---------------- packed fp32x2 helpers (Blackwell FFMA2 via PTX) -----------
__device__ __forceinline__ void ffma2(unsigned long long& d,
                                      unsigned long long a,
                                      unsigned long long b) {
    asm("fma.rn.f32x2 %0, %1, %2, %0;" : "+l"(d) : "l"(a), "l"(b));
}
__device__ __forceinline__ unsigned long long pack2(float x) {
    unsigned long long r;
    asm("mov.b64 %0, {%1, %1};" : "=l"(r) : "f"(x));
    return r;
}
__device__ __forceinline__ float2 unpack2(unsigned long long v) {
    float2 o;
    asm("mov.b64 {%0, %1}, %2;" : "=f"(o.x), "=f"(o.y) : "l"(v));
    return o;
}

// ---------------- bucket build ----------------------------------------------
__global__ void zero_counts_kernel() {
    int i = blockIdx.x * blockDim.x + threadIdx.x;
    if (i < NN) { g_cnt[i] = 0; g_asum[i] = 0.f; g_ascnt[i] = 0; }
}

// one pass: bucket scatter + per-dst non-self attr sum/count.
// 4 edges per thread, loads front-batched for MLP against DRAM latency.
__global__ void scatter_kernel(const int* __restrict__ ei,
                               const float* __restrict__ eattr, int E) {
    int T = gridDim.x * blockDim.x;
    int t = blockIdx.x * blockDim.x + threadIdx.x;
    int   s[4], d[4];
    float a[4];
    bool  v[4];
    #pragma unroll
    for (int j = 0; j < 4; ++j) {
        int e = t + j * T;
        v[j] = (e < E);
        int ec = v[j] ? e : 0;
        s[j] = ei[ec];
        d[j] = ei[E + ec];
        a[j] = eattr[ec];
    }
    #pragma unroll
    for (int j = 0; j < 4; ++j) {
        if (!v[j] || d[j] < 0 || d[j] >= NN) continue;
        int pos = atomicAdd(&g_cnt[d[j]], 1);
        if (pos < CAP)
            g_ecsr[d[j] * CAP + pos] = make_int2(s[j], __float_as_int(a[j]));
        if (s[j] != d[j]) {
            atomicAdd(&g_asum[d[j]], a[j]);
            atomicAdd(&g_ascnt[d[j]], 1);
        }
    }
}

// ---------------- fused dual SGEMM (FFMA2 inner, R9 known good) -------------
__global__ __launch_bounds__(256)
void sgemm_dual_bias(const float* __restrict__ A,
                     const float* __restrict__ Bl, const float* __restrict__ Br,
                     const float* __restrict__ bl, const float* __restrict__ br,
                     float* __restrict__ CL, float* __restrict__ CR,
                     int M, int N, int K) {
    __shared__ float As [16][64];
    __shared__ float Bls[16][64];
    __shared__ float Brs[16][64];
    int tid = threadIdx.x;
    int tx = tid & 15, ty = tid >> 4;
    int bm = blockIdx.x, bn = blockIdx.y;
    int rowBase = bm * 64;

    int aRow = tid >> 2;
    int aK   = (tid & 3) * 4;
    int bK   = tid >> 4;
    int bN   = (tid & 15) * 4;

    unsigned long long accL[4][2] = {};
    unsigned long long accR[4][2] = {};

    for (int k0 = 0; k0 < K; k0 += 16) {
        float4 av;
        int gr = rowBase + aRow;
        if (gr < M) av = *(const float4*)&A[(long)gr * K + k0 + aK];
        else        av = make_float4(0.f, 0.f, 0.f, 0.f);
        As[aK + 0][aRow] = av.x;
        As[aK + 1][aRow] = av.y;
        As[aK + 2][aRow] = av.z;
        As[aK + 3][aRow] = av.w;
        long boff = (long)(k0 + bK) * N + bn * 64 + bN;
        *(float4*)&Bls[bK][bN] = *(const float4*)&Bl[boff];
        *(float4*)&Brs[bK][bN] = *(const float4*)&Br[boff];
        __syncthreads();
        #pragma unroll
        for (int kk = 0; kk < 16; ++kk) {
            float4 a4 = *(const float4*)&As[kk][ty * 4];
            ulonglong2 blp = *(const ulonglong2*)&Bls[kk][tx * 4];
            ulonglong2 brp = *(const ulonglong2*)&Brs[kk][tx * 4];
            unsigned long long ap[4];
            ap[0] = pack2(a4.x); ap[1] = pack2(a4.y);
            ap[2] = pack2(a4.z); ap[3] = pack2(a4.w);
            #pragma unroll
            for (int i = 0; i < 4; ++i) {
                ffma2(accL[i][0], ap[i], blp.x);
                ffma2(accL[i][1], ap[i], blp.y);
                ffma2(accR[i][0], ap[i], brp.x);
                ffma2(accR[i][1], ap[i], brp.y);
            }
        }
        __syncthreads();
    }
    float4 bl4 = *(const float4*)&bl[bn * 64 + tx * 4];
    float4 br4 = *(const float4*)&br[bn * 64 + tx * 4];
    #pragma unroll
    for (int i = 0; i < 4; ++i) {
        int gr = rowBase + ty * 4 + i;
        if (gr < M) {
            float2 l0 = unpack2(accL[i][0]);
            float2 l1 = unpack2(accL[i][1]);
            float2 r0 = unpack2(accR[i][0]);
            float2 r1 = unpack2(accR[i][1]);
            float4 ol, orr;
            ol.x  = l0.x + bl4.x; ol.y  = l0.y + bl4.y;
            ol.z  = l1.x + bl4.z; ol.w  = l1.y + bl4.w;
            orr.x = r0.x + br4.x; orr.y = r0.y + br4.y;
            orr.z = r1.x + br4.z; orr.w = r1.y + br4.w;
            long coff = (long)gr * N + bn * 64 + tx * 4;
            *(float4*)&CL[coff] = ol;
            *(float4*)&CR[coff] = orr;
        }
    }
}

// ---------------- single SGEMM (output projection), FFMA2 inner -------------
__global__ __launch_bounds__(256)
void sgemm_bias(const float* __restrict__ A, const float* __restrict__ B,
                const float* __restrict__ bias, float* __restrict__ C,
                int M, int N, int K) {
    __shared__ float As[16][64];
    __shared__ float Bs[16][64];
    int tid = threadIdx.x;
    int tx = tid & 15, ty = tid >> 4;
    int bm = blockIdx.x, bn = blockIdx.y;
    int rowBase = bm * 64;

    int aRow = tid >> 2;
    int aK   = (tid & 3) * 4;
    int bK   = tid >> 4;
    int bN   = (tid & 15) * 4;

    unsigned long long acc[4][2] = {};
    for (int k0 = 0; k0 < K; k0 += 16) {
        float4 av;
        int gr = rowBase + aRow;
        if (gr < M) av = *(const float4*)&A[(long)gr * K + k0 + aK];
        else        av = make_float4(0.f, 0.f, 0.f, 0.f);
        As[aK + 0][aRow] = av.x;
        As[aK + 1][aRow] = av.y;
        As[aK + 2][aRow] = av.z;
        As[aK + 3][aRow] = av.w;
        *(float4*)&Bs[bK][bN] = *(const float4*)&B[(long)(k0 + bK) * N + bn * 64 + bN];
        __syncthreads();
        #pragma unroll
        for (int kk = 0; kk < 16; ++kk) {
            float4 a4 = *(const float4*)&As[kk][ty * 4];
            ulonglong2 bp = *(const ulonglong2*)&Bs[kk][tx * 4];
            unsigned long long ap[4];
            ap[0] = pack2(a4.x); ap[1] = pack2(a4.y);
            ap[2] = pack2(a4.z); ap[3] = pack2(a4.w);
            #pragma unroll
            for (int i = 0; i < 4; ++i) {
                ffma2(acc[i][0], ap[i], bp.x);
                ffma2(acc[i][1], ap[i], bp.y);
            }
        }
        __syncthreads();
    }
    float4 bias4 = *(const float4*)&bias[bn * 64 + tx * 4];
    #pragma unroll
    for (int i = 0; i < 4; ++i) {
        int gr = rowBase + ty * 4 + i;
        if (gr < M) {
            float2 c0 = unpack2(acc[i][0]);
            float2 c1 = unpack2(acc[i][1]);
            float4 o;
            o.x = c0.x + bias4.x;
            o.y = c0.y + bias4.y;
            o.z = c1.x + bias4.z;
            o.w = c1.y + bias4.w;
            *(float4*)&C[(long)gr * N + bn * 64 + tx * 4] = o;
        }
    }
}

// ---------------- GATv2 edge phase: one warp per dst node ------------------
// R11 structure; bucket range beg = n*CAP, end = beg + min(cnt, CAP).
__device__ __forceinline__ float leaky02(float m) {
    return fmaxf(m, 0.f) + 0.2f * fminf(m, 0.f);
}

__global__ __launch_bounds__(256)
void gat_edge_kernel(const float* __restrict__ XL, const float* __restrict__ XR,
                     const float* __restrict__ att, const float* __restrict__ We,
                     const float* __restrict__ bias, float* __restrict__ out,
                     int applyElu) {
    int gid  = blockIdx.x * blockDim.x + threadIdx.x;
    int n    = gid >> 5;
    int lane = gid & 31;
    if (n >= NN) return;

    int base = (lane >> 3) * CH + (lane & 7) * 4;   // head*32 + chan4
    float4 xr4 = *(const float4*)&XR[n * HCC + base];
    float4 at4 = *(const float4*)&att[base];
    float4 we4 = *(const float4*)&We[base];

    float mx = -CUDART_INF_F, dn = 0.f;
    float4 acc = make_float4(0.f, 0.f, 0.f, 0.f);

    int deg = g_cnt[n];
    if (deg > CAP) deg = CAP;            // memory safety (never hit in practice)
    int beg = n * CAP, end = beg + deg;

    int2   edC = make_int2(0, 0), edN = make_int2(0, 0);
    float4 xlC = make_float4(0.f, 0.f, 0.f, 0.f);
    int last = end - 1;
    if (beg < end) {
        edC = g_ecsr[beg];
        edN = g_ecsr[(beg + 1 < end) ? (beg + 1) : last];
        xlC = *(const float4*)&XL[(long)edC.x * HCC + base];
    }

    for (int e = beg; e < end; ++e) {
        // issue next-edge gather immediately (descriptor already resident)
        float4 xlN = *(const float4*)&XL[(long)edN.x * HCC + base];
        int i2 = e + 2;
        int2 edNN = g_ecsr[(i2 < end) ? i2 : last];
        // process current edge
        if (edC.x != n) {                           // PyG self-loop removal
            float ae = __int_as_float(edC.y);
            float p = leaky02(fmaf(ae, we4.x, xlC.x + xr4.x)) * at4.x
                    + leaky02(fmaf(ae, we4.y, xlC.y + xr4.y)) * at4.y
                    + leaky02(fmaf(ae, we4.z, xlC.z + xr4.z)) * at4.z
                    + leaky02(fmaf(ae, we4.w, xlC.w + xr4.w)) * at4.w;
            p += __shfl_xor_sync(0xffffffffu, p, 4);
            p += __shfl_xor_sync(0xffffffffu, p, 2);
            p += __shfl_xor_sync(0xffffffffu, p, 1);
            if (p > mx) {
                float r = __expf(mx - p);           // exp(-inf)=0 first time
                dn *= r;
                acc.x *= r; acc.y *= r; acc.z *= r; acc.w *= r;
                mx = p;
            }
            float w = __expf(p - mx);
            dn += w;
            acc.x = fmaf(w, xlC.x, acc.x);
            acc.y = fmaf(w, xlC.y, acc.y);
            acc.z = fmaf(w, xlC.z, acc.z);
            acc.w = fmaf(w, xlC.w, acc.w);
        }
        edC = edN; edN = edNN; xlC = xlN;
    }

    // self loop (always added, edge_attr = mean of incoming non-self attrs)
    {
        int   c  = g_ascnt[n];
        float la = (c > 0) ? g_asum[n] / (float)c : 0.f;
        float4 xl4 = *(const float4*)&XL[n * HCC + base];
        float p = leaky02(fmaf(la, we4.x, xl4.x + xr4.x)) * at4.x
                + leaky02(fmaf(la, we4.y, xl4.y + xr4.y)) * at4.y
                + leaky02(fmaf(la, we4.z, xl4.z + xr4.z)) * at4.z
                + leaky02(fmaf(la, we4.w, xl4.w + xr4.w)) * at4.w;
        p += __shfl_xor_sync(0xffffffffu, p, 4);
        p += __shfl_xor_sync(0xffffffffu, p, 2);
        p += __shfl_xor_sync(0xffffffffu, p, 1);
        if (p > mx) {
            float r = __expf(mx - p);
            dn *= r;
            acc.x *= r; acc.y *= r; acc.z *= r; acc.w *= r;
            mx = p;
        }
        float w = __expf(p - mx);
        dn += w;
        acc.x = fmaf(w, xl4.x, acc.x);
        acc.y = fmaf(w, xl4.y, acc.y);
        acc.z = fmaf(w, xl4.z, acc.z);
        acc.w = fmaf(w, xl4.w, acc.w);
    }

    float4 b4 = *(const float4*)&bias[base];
    float inv = 1.f / dn;
    float4 o;
    o.x = fmaf(acc.x, inv, b4.x);
    o.y = fmaf(acc.y, inv, b4.y);
    o.z = fmaf(acc.z, inv, b4.z);
    o.w = fmaf(acc.w, inv, b4.w);
    if (applyElu) {
        o.x = (o.x > 0.f) ? o.x : (__expf(o.x) - 1.f);
        o.y = (o.y > 0.f) ? o.y : (__expf(o.y) - 1.f);
        o.z = (o.z > 0.f) ? o.z : (__expf(o.z) - 1.f);
        o.w = (o.w > 0.f) ? o.w : (__expf(o.w) - 1.f);
    }
    *(float4*)&out[n * HCC + base] = o;
}

// ---------------- launch ----------------------------------------------------
extern "C" void kernel_launch(void* const* d_in, const int* in_sizes, int n_in,
                              void* d_out, int out_size) {
    const float* x     = (const float*)d_in[0];
    const int*   ei    = (const int*)d_in[1];
    const float* eattr = (const float*)d_in[2];
    const float* Wl1 = (const float*)d_in[3];
    const float* bl1 = (const float*)d_in[4];
    const float* Wr1 = (const float*)d_in[5];
    const float* br1 = (const float*)d_in[6];
    const float* We1 = (const float*)d_in[7];
    const float* att1= (const float*)d_in[8];
    const float* b1  = (const float*)d_in[9];
    const float* Wl2 = (const float*)d_in[10];
    const float* bl2 = (const float*)d_in[11];
    const float* Wr2 = (const float*)d_in[12];
    const float* br2 = (const float*)d_in[13];
    const float* We2 = (const float*)d_in[14];
    const float* att2= (const float*)d_in[15];
    const float* b2  = (const float*)d_in[16];
    const float* Wo  = (const float*)d_in[17];
    const float* bo  = (const float*)d_in[18];
    float* out = (float*)d_out;

    int E = in_sizes[1] / 2;        // 640000
    int N = in_sizes[0] / HCC;      // 20000

    float *XL, *XR, *H;
    cudaGetSymbolAddress((void**)&XL, g_XL);
    cudaGetSymbolAddress((void**)&XR, g_XR);
    cudaGetSymbolAddress((void**)&H,  g_H);

    // secondary stream + events for bucket-build || GEMM1 overlap
    static cudaStream_t s1 = nullptr;
    static cudaEvent_t evFork = nullptr, evJoin = nullptr;
    if (s1 == nullptr) {
        cudaStreamCreateWithFlags(&s1, cudaStreamNonBlocking);
        cudaEventCreateWithFlags(&evFork, cudaEventDisableTiming);
        cudaEventCreateWithFlags(&evJoin, cudaEventDisableTiming);
    }

    dim3 gemmGrid((N + 63) / 64, HCC / 64);
    dim3 gemmGridOut((N + 63) / 64, DOUT / 64);
    int edgeBlocks = (N * 32 + 255) / 256;   // one warp per node
    int sBlocks    = ((E + 3) / 4 + 255) / 256;  // 4 edges per thread
    int nBlocks    = (N + 255) / 256;

    // ---- fork: bucket build on s1, layer-1 GEMM on main stream
    cudaEventRecord(evFork, 0);
    cudaStreamWaitEvent(s1, evFork, 0);

    zero_counts_kernel<<<nBlocks, 256, 0, s1>>>();
    scatter_kernel<<<sBlocks, 256, 0, s1>>>(ei, eattr, E);
    cudaEventRecord(evJoin, s1);

    sgemm_dual_bias<<<gemmGrid, 256>>>(x, Wl1, Wr1, bl1, br1, XL, XR, N, HCC, HCC);

    cudaStreamWaitEvent(0, evJoin, 0);

    // layer 1 edge phase
    gat_edge_kernel<<<edgeBlocks, 256>>>(XL, XR, att1, We1, b1, H, 1);

    // layer 2
    sgemm_dual_bias<<<gemmGrid, 256>>>(H, Wl2, Wr2, bl2, br2, XL, XR, N, HCC, HCC);
    gat_edge_kernel<<<edgeBlocks, 256>>>(XL, XR, att2, We2, b2, H, 1);

    // output projection
    sgemm_bias<<<gemmGridOut, 256>>>(H, Wo, bo, out, N, DOUT, HCC);
}

// round 13
// speedup vs baseline: 1.3462x; 1.3462x over previous
#include <cuda_runtime.h>
#include <math_constants.h>

// Problem constants (fixed by the dataset)
#define NN   20000      // nodes
#define EE   640000     // edges
#define HCC  128        // H * C
#define NH   4          // heads
#define CH   32         // channels per head
#define DOUT 64

// ---------------- device scratch (static: no allocations allowed) -----------
__device__ float g_XL[NN * HCC];
__device__ float g_XR[NN * HCC];
__device__ float g_H [NN * HCC];
__device__ int   g_cnt[NN];
__device__ int   g_cur[NN];
__device__ float g_asum[NN];     // sum of non-self incoming edge_attr
__device__ int   g_ascnt[NN];    // count of non-self incoming edges
__device__ int   g_rowptr[NN + 1];
__device__ int2  g_ecsr[EE];     // packed (src, edge_attr bits), CSR order by dst

// ---------------- packed fp32x2 helpers (Blackwell, compile-proven R9) ------
typedef unsigned long long ull;
__device__ __forceinline__ void ffma2(ull& d, ull a, ull b) {
    asm("fma.rn.f32x2 %0, %1, %2, %0;" : "+l"(d) : "l"(a), "l"(b));
}
__device__ __forceinline__ ull fma2v(ull a, ull b, ull c) {
    ull d;
    asm("fma.rn.f32x2 %0, %1, %2, %3;" : "=l"(d) : "l"(a), "l"(b), "l"(c));
    return d;
}
__device__ __forceinline__ ull add2(ull a, ull b) {
    ull d;
    asm("add.rn.f32x2 %0, %1, %2;" : "=l"(d) : "l"(a), "l"(b));
    return d;
}
__device__ __forceinline__ ull mul2(ull a, ull b) {
    ull d;
    asm("mul.rn.f32x2 %0, %1, %2;" : "=l"(d) : "l"(a), "l"(b));
    return d;
}
__device__ __forceinline__ ull pack2(float x) {
    ull r;
    asm("mov.b64 %0, {%1, %1};" : "=l"(r) : "f"(x));
    return r;
}
__device__ __forceinline__ float2 unpack2(ull v) {
    float2 o;
    asm("mov.b64 {%0, %1}, %2;" : "=f"(o.x), "=f"(o.y) : "l"(v));
    return o;
}

// ---------------- CSR build (R11, known good) -------------------------------
__global__ void zero_counts_kernel() {
    int i = blockIdx.x * blockDim.x + threadIdx.x;
    if (i < NN) { g_cnt[i] = 0; g_cur[i] = 0; g_asum[i] = 0.f; g_ascnt[i] = 0; }
}

__global__ void hist_kernel(const int* __restrict__ ei,
                            const float* __restrict__ eattr, int E) {
    int stride = gridDim.x * blockDim.x;
    for (int e = blockIdx.x * blockDim.x + threadIdx.x; e < E; e += stride) {
        int s = ei[e];
        int d = ei[E + e];
        if (d < 0 || d >= NN) continue;
        atomicAdd(&g_cnt[d], 1);
        if (s != d) {
            atomicAdd(&g_asum[d], eattr[e]);
            atomicAdd(&g_ascnt[d], 1);
        }
    }
}

__global__ void scan_kernel(int n) {
    __shared__ int sums[1024];
    int tid = threadIdx.x;
    int per = (n + 1023) >> 10;
    int beg = tid * per;
    int end = beg + per;
    if (beg > n) beg = n;
    if (end > n) end = n;
    int s = 0;
    for (int i = beg; i < end; ++i) s += g_cnt[i];
    sums[tid] = s;
    __syncthreads();
    for (int off = 1; off < 1024; off <<= 1) {
        int v = (tid >= off) ? sums[tid - off] : 0;
        __syncthreads();
        sums[tid] += v;
        __syncthreads();
    }
    int run = (tid == 0) ? 0 : sums[tid - 1];
    for (int i = beg; i < end; ++i) { g_rowptr[i] = run; run += g_cnt[i]; }
    if (tid == 0) g_rowptr[n] = sums[1023];
}

__global__ void scatter_kernel(const int* __restrict__ ei,
                               const float* __restrict__ eattr, int E) {
    int stride = gridDim.x * blockDim.x;
    for (int e = blockIdx.x * blockDim.x + threadIdx.x; e < E; e += stride) {
        int dst = ei[E + e];
        if (dst < 0 || dst >= NN) continue;
        int pos = g_rowptr[dst] + atomicAdd(&g_cur[dst], 1);
        g_ecsr[pos] = make_int2(ei[e], __float_as_int(eattr[e]));
    }
}

// ---------------- fused dual SGEMM (FFMA2 inner, R9 known good) -------------
__global__ __launch_bounds__(256)
void sgemm_dual_bias(const float* __restrict__ A,
                     const float* __restrict__ Bl, const float* __restrict__ Br,
                     const float* __restrict__ bl, const float* __restrict__ br,
                     float* __restrict__ CL, float* __restrict__ CR,
                     int M, int N, int K) {
    __shared__ float As [16][64];
    __shared__ float Bls[16][64];
    __shared__ float Brs[16][64];
    int tid = threadIdx.x;
    int tx = tid & 15, ty = tid >> 4;
    int bm = blockIdx.x, bn = blockIdx.y;
    int rowBase = bm * 64;

    int aRow = tid >> 2;
    int aK   = (tid & 3) * 4;
    int bK   = tid >> 4;
    int bN   = (tid & 15) * 4;

    ull accL[4][2] = {};
    ull accR[4][2] = {};

    for (int k0 = 0; k0 < K; k0 += 16) {
        float4 av;
        int gr = rowBase + aRow;
        if (gr < M) av = *(const float4*)&A[(long)gr * K + k0 + aK];
        else        av = make_float4(0.f, 0.f, 0.f, 0.f);
        As[aK + 0][aRow] = av.x;
        As[aK + 1][aRow] = av.y;
        As[aK + 2][aRow] = av.z;
        As[aK + 3][aRow] = av.w;
        long boff = (long)(k0 + bK) * N + bn * 64 + bN;
        *(float4*)&Bls[bK][bN] = *(const float4*)&Bl[boff];
        *(float4*)&Brs[bK][bN] = *(const float4*)&Br[boff];
        __syncthreads();
        #pragma unroll
        for (int kk = 0; kk < 16; ++kk) {
            float4 a4 = *(const float4*)&As[kk][ty * 4];
            ulonglong2 blp = *(const ulonglong2*)&Bls[kk][tx * 4];
            ulonglong2 brp = *(const ulonglong2*)&Brs[kk][tx * 4];
            ull ap[4];
            ap[0] = pack2(a4.x); ap[1] = pack2(a4.y);
            ap[2] = pack2(a4.z); ap[3] = pack2(a4.w);
            #pragma unroll
            for (int i = 0; i < 4; ++i) {
                ffma2(accL[i][0], ap[i], blp.x);
                ffma2(accL[i][1], ap[i], blp.y);
                ffma2(accR[i][0], ap[i], brp.x);
                ffma2(accR[i][1], ap[i], brp.y);
            }
        }
        __syncthreads();
    }
    float4 bl4 = *(const float4*)&bl[bn * 64 + tx * 4];
    float4 br4 = *(const float4*)&br[bn * 64 + tx * 4];
    #pragma unroll
    for (int i = 0; i < 4; ++i) {
        int gr = rowBase + ty * 4 + i;
        if (gr < M) {
            float2 l0 = unpack2(accL[i][0]);
            float2 l1 = unpack2(accL[i][1]);
            float2 r0 = unpack2(accR[i][0]);
            float2 r1 = unpack2(accR[i][1]);
            float4 ol, orr;
            ol.x  = l0.x + bl4.x; ol.y  = l0.y + bl4.y;
            ol.z  = l1.x + bl4.z; ol.w  = l1.y + bl4.w;
            orr.x = r0.x + br4.x; orr.y = r0.y + br4.y;
            orr.z = r1.x + br4.z; orr.w = r1.y + br4.w;
            long coff = (long)gr * N + bn * 64 + tx * 4;
            *(float4*)&CL[coff] = ol;
            *(float4*)&CR[coff] = orr;
        }
    }
}

// ---------------- single SGEMM (output projection), FFMA2 inner -------------
__global__ __launch_bounds__(256)
void sgemm_bias(const float* __restrict__ A, const float* __restrict__ B,
                const float* __restrict__ bias, float* __restrict__ C,
                int M, int N, int K) {
    __shared__ float As[16][64];
    __shared__ float Bs[16][64];
    int tid = threadIdx.x;
    int tx = tid & 15, ty = tid >> 4;
    int bm = blockIdx.x, bn = blockIdx.y;
    int rowBase = bm * 64;

    int aRow = tid >> 2;
    int aK   = (tid & 3) * 4;
    int bK   = tid >> 4;
    int bN   = (tid & 15) * 4;

    ull acc[4][2] = {};
    for (int k0 = 0; k0 < K; k0 += 16) {
        float4 av;
        int gr = rowBase + aRow;
        if (gr < M) av = *(const float4*)&A[(long)gr * K + k0 + aK];
        else        av = make_float4(0.f, 0.f, 0.f, 0.f);
        As[aK + 0][aRow] = av.x;
        As[aK + 1][aRow] = av.y;
        As[aK + 2][aRow] = av.z;
        As[aK + 3][aRow] = av.w;
        *(float4*)&Bs[bK][bN] = *(const float4*)&B[(long)(k0 + bK) * N + bn * 64 + bN];
        __syncthreads();
        #pragma unroll
        for (int kk = 0; kk < 16; ++kk) {
            float4 a4 = *(const float4*)&As[kk][ty * 4];
            ulonglong2 bp = *(const ulonglong2*)&Bs[kk][tx * 4];
            ull ap[4];
            ap[0] = pack2(a4.x); ap[1] = pack2(a4.y);
            ap[2] = pack2(a4.z); ap[3] = pack2(a4.w);
            #pragma unroll
            for (int i = 0; i < 4; ++i) {
                ffma2(acc[i][0], ap[i], bp.x);
                ffma2(acc[i][1], ap[i], bp.y);
            }
        }
        __syncthreads();
    }
    float4 bias4 = *(const float4*)&bias[bn * 64 + tx * 4];
    #pragma unroll
    for (int i = 0; i < 4; ++i) {
        int gr = rowBase + ty * 4 + i;
        if (gr < M) {
            float2 c0 = unpack2(acc[i][0]);
            float2 c1 = unpack2(acc[i][1]);
            float4 o;
            o.x = c0.x + bias4.x;
            o.y = c0.y + bias4.y;
            o.z = c1.x + bias4.z;
            o.w = c1.y + bias4.w;
            *(float4*)&C[(long)gr * N + bn * 64 + tx * 4] = o;
        }
    }
}

// ---------------- GATv2 edge phase: one warp per dst node ------------------
// Issue-bound (ncu R12: issue=73.5%). Slimmed arithmetic:
//  - leaky(m) = max(m, 0.2m)  (2 ops/channel)
//  - packed f32x2 add/fma for m and acc
//  - 2x-unrolled prefetch pipeline (halves loop-carried shifts)
__global__ __launch_bounds__(256)
void gat_edge_kernel(const float* __restrict__ XL, const float* __restrict__ XR,
                     const float* __restrict__ att, const float* __restrict__ We,
                     const float* __restrict__ bias, float* __restrict__ out,
                     int applyElu) {
    int gid  = blockIdx.x * blockDim.x + threadIdx.x;
    int n    = gid >> 5;
    int lane = gid & 31;
    if (n >= NN) return;

    int base = (lane >> 3) * CH + (lane & 7) * 4;   // head*32 + chan4
    float4 xr4 = *(const float4*)&XR[n * HCC + base];
    float4 at4 = *(const float4*)&att[base];
    float4 we4 = *(const float4*)&We[base];
    ulonglong2 xr2 = *(ulonglong2*)&xr4;
    ulonglong2 we2 = *(ulonglong2*)&we4;

    float mx = -CUDART_INF_F, dn = 0.f;
    ull acc0 = 0, acc1 = 0;                         // packed 2+2 channels

    int beg = g_rowptr[n], end = g_rowptr[n + 1];
    int last = end - 1;

#define PROC_EDGE(ED, XLV) do {                                               \
    if ((ED).x != n) {                                                        \
        ulonglong2 xl2 = *(ulonglong2*)&(XLV);                                \
        ull ae2 = pack2(__int_as_float((ED).y));                              \
        ull m0 = fma2v(ae2, we2.x, add2(xl2.x, xr2.x));                       \
        ull m1 = fma2v(ae2, we2.y, add2(xl2.y, xr2.y));                       \
        float2 ma = unpack2(m0), mb = unpack2(m1);                            \
        float l0 = fmaxf(ma.x, 0.2f * ma.x);                                  \
        float l1 = fmaxf(ma.y, 0.2f * ma.y);                                  \
        float l2 = fmaxf(mb.x, 0.2f * mb.x);                                  \
        float l3 = fmaxf(mb.y, 0.2f * mb.y);                                  \
        float p = fmaf(l3, at4.w, fmaf(l2, at4.z, fmaf(l1, at4.y, l0 * at4.x))); \
        p += __shfl_xor_sync(0xffffffffu, p, 4);                              \
        p += __shfl_xor_sync(0xffffffffu, p, 2);                              \
        p += __shfl_xor_sync(0xffffffffu, p, 1);                              \
        if (p > mx) {                                                         \
            float r = __expf(mx - p);                                         \
            ull r2 = pack2(r);                                                \
            dn *= r;                                                          \
            acc0 = mul2(acc0, r2);                                            \
            acc1 = mul2(acc1, r2);                                            \
            mx = p;                                                           \
        }                                                                     \
        float w = __expf(p - mx);                                             \
        dn += w;                                                              \
        ull w2 = pack2(w);                                                    \
        acc0 = fma2v(w2, xl2.x, acc0);                                        \
        acc1 = fma2v(w2, xl2.y, acc1);                                        \
    }                                                                         \
} while (0)

    if (beg < end) {
        int2 edA = g_ecsr[beg];
        int2 edB = g_ecsr[(beg + 1 < end) ? (beg + 1) : last];
        float4 xlA = *(const float4*)&XL[(long)edA.x * HCC + base];
        int e = beg;
        while (true) {
            float4 xlB = *(const float4*)&XL[(long)edB.x * HCC + base];
            int i2 = e + 2;
            int2 edC = g_ecsr[(i2 < end) ? i2 : last];
            PROC_EDGE(edA, xlA);
            if (++e >= end) break;

            float4 xlC = *(const float4*)&XL[(long)edC.x * HCC + base];
            int i3 = e + 2;
            int2 edD = g_ecsr[(i3 < end) ? i3 : last];
            PROC_EDGE(edB, xlB);
            if (++e >= end) break;

            edA = edC; edB = edD; xlA = xlC;
        }
    }
#undef PROC_EDGE

    // self loop (always added, edge_attr = mean of incoming non-self attrs)
    {
        int   c  = g_ascnt[n];
        float la = (c > 0) ? g_asum[n] / (float)c : 0.f;
        float4 xl4 = *(const float4*)&XL[n * HCC + base];
        ulonglong2 xl2 = *(ulonglong2*)&xl4;
        ull la2 = pack2(la);
        ull m0 = fma2v(la2, we2.x, add2(xl2.x, xr2.x));
        ull m1 = fma2v(la2, we2.y, add2(xl2.y, xr2.y));
        float2 ma = unpack2(m0), mb = unpack2(m1);
        float l0 = fmaxf(ma.x, 0.2f * ma.x);
        float l1 = fmaxf(ma.y, 0.2f * ma.y);
        float l2 = fmaxf(mb.x, 0.2f * mb.x);
        float l3 = fmaxf(mb.y, 0.2f * mb.y);
        float p = fmaf(l3, at4.w, fmaf(l2, at4.z, fmaf(l1, at4.y, l0 * at4.x)));
        p += __shfl_xor_sync(0xffffffffu, p, 4);
        p += __shfl_xor_sync(0xffffffffu, p, 2);
        p += __shfl_xor_sync(0xffffffffu, p, 1);
        if (p > mx) {
            float r = __expf(mx - p);
            ull r2 = pack2(r);
            dn *= r;
            acc0 = mul2(acc0, r2);
            acc1 = mul2(acc1, r2);
            mx = p;
        }
        float w = __expf(p - mx);
        dn += w;
        ull w2 = pack2(w);
        acc0 = fma2v(w2, xl2.x, acc0);
        acc1 = fma2v(w2, xl2.y, acc1);
    }

    float4 b4 = *(const float4*)&bias[base];
    float inv = 1.f / dn;
    float2 a01 = unpack2(acc0);
    float2 a23 = unpack2(acc1);
    float4 o;
    o.x = fmaf(a01.x, inv, b4.x);
    o.y = fmaf(a01.y, inv, b4.y);
    o.z = fmaf(a23.x, inv, b4.z);
    o.w = fmaf(a23.y, inv, b4.w);
    if (applyElu) {
        o.x = (o.x > 0.f) ? o.x : (__expf(o.x) - 1.f);
        o.y = (o.y > 0.f) ? o.y : (__expf(o.y) - 1.f);
        o.z = (o.z > 0.f) ? o.z : (__expf(o.z) - 1.f);
        o.w = (o.w > 0.f) ? o.w : (__expf(o.w) - 1.f);
    }
    *(float4*)&out[n * HCC + base] = o;
}

// ---------------- launch ----------------------------------------------------
extern "C" void kernel_launch(void* const* d_in, const int* in_sizes, int n_in,
                              void* d_out, int out_size) {
    const float* x     = (const float*)d_in[0];
    const int*   ei    = (const int*)d_in[1];
    const float* eattr = (const float*)d_in[2];
    const float* Wl1 = (const float*)d_in[3];
    const float* bl1 = (const float*)d_in[4];
    const float* Wr1 = (const float*)d_in[5];
    const float* br1 = (const float*)d_in[6];
    const float* We1 = (const float*)d_in[7];
    const float* att1= (const float*)d_in[8];
    const float* b1  = (const float*)d_in[9];
    const float* Wl2 = (const float*)d_in[10];
    const float* bl2 = (const float*)d_in[11];
    const float* Wr2 = (const float*)d_in[12];
    const float* br2 = (const float*)d_in[13];
    const float* We2 = (const float*)d_in[14];
    const float* att2= (const float*)d_in[15];
    const float* b2  = (const float*)d_in[16];
    const float* Wo  = (const float*)d_in[17];
    const float* bo  = (const float*)d_in[18];
    float* out = (float*)d_out;

    int E = in_sizes[1] / 2;        // 640000
    int N = in_sizes[0] / HCC;      // 20000

    float *XL, *XR, *H;
    cudaGetSymbolAddress((void**)&XL, g_XL);
    cudaGetSymbolAddress((void**)&XR, g_XR);
    cudaGetSymbolAddress((void**)&H,  g_H);

    // secondary stream + events for CSR || GEMM1 overlap
    static cudaStream_t s1 = nullptr;
    static cudaEvent_t evFork = nullptr, evJoin = nullptr;
    if (s1 == nullptr) {
        cudaStreamCreateWithFlags(&s1, cudaStreamNonBlocking);
        cudaEventCreateWithFlags(&evFork, cudaEventDisableTiming);
        cudaEventCreateWithFlags(&evJoin, cudaEventDisableTiming);
    }

    dim3 gemmGrid((N + 63) / 64, HCC / 64);
    dim3 gemmGridOut((N + 63) / 64, DOUT / 64);
    int edgeBlocks = (N * 32 + 255) / 256;   // one warp per node
    int eBlocks2   = (E / 2 + 255) / 256;    // grid-stride x2 (MLP)
    int nBlocks    = (N + 255) / 256;

    // ---- fork: CSR build on s1, layer-1 GEMM on main stream
    cudaEventRecord(evFork, 0);
    cudaStreamWaitEvent(s1, evFork, 0);

    zero_counts_kernel<<<nBlocks, 256, 0, s1>>>();
    hist_kernel<<<eBlocks2, 256, 0, s1>>>(ei, eattr, E);
    scan_kernel<<<1, 1024, 0, s1>>>(N);
    scatter_kernel<<<eBlocks2, 256, 0, s1>>>(ei, eattr, E);
    cudaEventRecord(evJoin, s1);

    sgemm_dual_bias<<<gemmGrid, 256>>>(x, Wl1, Wr1, bl1, br1, XL, XR, N, HCC, HCC);

    cudaStreamWaitEvent(0, evJoin, 0);

    // layer 1 edge phase
    gat_edge_kernel<<<edgeBlocks, 256>>>(XL, XR, att1, We1, b1, H, 1);

    // layer 2
    sgemm_dual_bias<<<gemmGrid, 256>>>(H, Wl2, Wr2, bl2, br2, XL, XR, N, HCC, HCC);
    gat_edge_kernel<<<edgeBlocks, 256>>>(XL, XR, att2, We2, b2, H, 1);

    // output projection
    sgemm_bias<<<gemmGridOut, 256>>>(H, Wo, bo, out, N, DOUT, HCC);
}

// round 14
// speedup vs baseline: 1.3530x; 1.0051x over previous
#include <cuda_runtime.h>
#include <math_constants.h>

// Problem constants (fixed by the dataset)
#define NN   20000      // nodes
#define EE   640000     // edges
#define HCC  128        // H * C
#define NH   4          // heads
#define CH   32         // channels per head
#define DOUT 64

// ---------------- device scratch (static: no allocations allowed) -----------
__device__ float g_XL[NN * HCC];
__device__ float g_XR[NN * HCC];
__device__ float g_H [NN * HCC];
__device__ int   g_cnt[NN];
__device__ int   g_cur[NN];
__device__ float g_asum[NN];       // sum of non-self incoming edge_attr
__device__ int   g_ascnt[NN];      // count of non-self incoming edges
__device__ int   g_rowptr[NN + 1];
__device__ int2  g_ecsr[EE + 8];   // non-self edges, CSR by dst; +8 zero-init pad
                                   // (lets the edge kernel prefetch unclamped)

// ---------------- packed fp32x2 helpers (Blackwell, compile-proven) ---------
typedef unsigned long long ull;
__device__ __forceinline__ void ffma2(ull& d, ull a, ull b) {
    asm("fma.rn.f32x2 %0, %1, %2, %0;" : "+l"(d) : "l"(a), "l"(b));
}
__device__ __forceinline__ ull fma2v(ull a, ull b, ull c) {
    ull d;
    asm("fma.rn.f32x2 %0, %1, %2, %3;" : "=l"(d) : "l"(a), "l"(b), "l"(c));
    return d;
}
__device__ __forceinline__ ull add2(ull a, ull b) {
    ull d;
    asm("add.rn.f32x2 %0, %1, %2;" : "=l"(d) : "l"(a), "l"(b));
    return d;
}
__device__ __forceinline__ ull pack2(float x) {
    ull r;
    asm("mov.b64 %0, {%1, %1};" : "=l"(r) : "f"(x));
    return r;
}
__device__ __forceinline__ float2 unpack2(ull v) {
    float2 o;
    asm("mov.b64 {%0, %1}, %2;" : "=f"(o.x), "=f"(o.y) : "l"(v));
    return o;
}

// ---------------- CSR build (self-edges filtered out here) ------------------
__global__ void zero_counts_kernel() {
    int i = blockIdx.x * blockDim.x + threadIdx.x;
    if (i < NN) { g_cnt[i] = 0; g_cur[i] = 0; g_asum[i] = 0.f; g_ascnt[i] = 0; }
}

// histogram (non-self only) + per-dst attr sum/count; 4-batched loads for MLP
__global__ void hist_kernel(const int* __restrict__ ei,
                            const float* __restrict__ eattr, int E) {
    int T = gridDim.x * blockDim.x;
    int t = blockIdx.x * blockDim.x + threadIdx.x;
    int   s[4], d[4];
    float a[4];
    bool  v[4];
    #pragma unroll
    for (int j = 0; j < 4; ++j) {
        int e = t + j * T;
        v[j] = (e < E);
        int ec = v[j] ? e : 0;
        s[j] = ei[ec];
        d[j] = ei[E + ec];
        a[j] = eattr[ec];
    }
    #pragma unroll
    for (int j = 0; j < 4; ++j) {
        if (!v[j] || d[j] < 0 || d[j] >= NN || s[j] == d[j]) continue;
        atomicAdd(&g_cnt[d[j]], 1);
        atomicAdd(&g_asum[d[j]], a[j]);
        atomicAdd(&g_ascnt[d[j]], 1);
    }
}

// single-block exclusive scan of g_cnt -> g_rowptr
__global__ void scan_kernel(int n) {
    __shared__ int sums[1024];
    int tid = threadIdx.x;
    int per = (n + 1023) >> 10;
    int beg = tid * per;
    int end = beg + per;
    if (beg > n) beg = n;
    if (end > n) end = n;
    int s = 0;
    for (int i = beg; i < end; ++i) s += g_cnt[i];
    sums[tid] = s;
    __syncthreads();
    for (int off = 1; off < 1024; off <<= 1) {
        int v = (tid >= off) ? sums[tid - off] : 0;
        __syncthreads();
        sums[tid] += v;
        __syncthreads();
    }
    int run = (tid == 0) ? 0 : sums[tid - 1];
    for (int i = beg; i < end; ++i) { g_rowptr[i] = run; run += g_cnt[i]; }
    if (tid == 0) g_rowptr[n] = sums[1023];
}

// scatter (non-self only); 4-batched loads
__global__ void scatter_kernel(const int* __restrict__ ei,
                               const float* __restrict__ eattr, int E) {
    int T = gridDim.x * blockDim.x;
    int t = blockIdx.x * blockDim.x + threadIdx.x;
    int   s[4], d[4];
    float a[4];
    bool  v[4];
    #pragma unroll
    for (int j = 0; j < 4; ++j) {
        int e = t + j * T;
        v[j] = (e < E);
        int ec = v[j] ? e : 0;
        s[j] = ei[ec];
        d[j] = ei[E + ec];
        a[j] = eattr[ec];
    }
    #pragma unroll
    for (int j = 0; j < 4; ++j) {
        if (!v[j] || d[j] < 0 || d[j] >= NN || s[j] == d[j]) continue;
        int pos = g_rowptr[d[j]] + atomicAdd(&g_cur[d[j]], 1);
        g_ecsr[pos] = make_int2(s[j], __float_as_int(a[j]));
    }
}

// ---------------- fused dual SGEMM (FFMA2 inner, known good) ----------------
__global__ __launch_bounds__(256)
void sgemm_dual_bias(const float* __restrict__ A,
                     const float* __restrict__ Bl, const float* __restrict__ Br,
                     const float* __restrict__ bl, const float* __restrict__ br,
                     float* __restrict__ CL, float* __restrict__ CR,
                     int M, int N, int K) {
    __shared__ float As [16][64];
    __shared__ float Bls[16][64];
    __shared__ float Brs[16][64];
    int tid = threadIdx.x;
    int tx = tid & 15, ty = tid >> 4;
    int bm = blockIdx.x, bn = blockIdx.y;
    int rowBase = bm * 64;

    int aRow = tid >> 2;
    int aK   = (tid & 3) * 4;
    int bK   = tid >> 4;
    int bN   = (tid & 15) * 4;

    ull accL[4][2] = {};
    ull accR[4][2] = {};

    for (int k0 = 0; k0 < K; k0 += 16) {
        float4 av;
        int gr = rowBase + aRow;
        if (gr < M) av = *(const float4*)&A[(long)gr * K + k0 + aK];
        else        av = make_float4(0.f, 0.f, 0.f, 0.f);
        As[aK + 0][aRow] = av.x;
        As[aK + 1][aRow] = av.y;
        As[aK + 2][aRow] = av.z;
        As[aK + 3][aRow] = av.w;
        long boff = (long)(k0 + bK) * N + bn * 64 + bN;
        *(float4*)&Bls[bK][bN] = *(const float4*)&Bl[boff];
        *(float4*)&Brs[bK][bN] = *(const float4*)&Br[boff];
        __syncthreads();
        #pragma unroll
        for (int kk = 0; kk < 16; ++kk) {
            float4 a4 = *(const float4*)&As[kk][ty * 4];
            ulonglong2 blp = *(const ulonglong2*)&Bls[kk][tx * 4];
            ulonglong2 brp = *(const ulonglong2*)&Brs[kk][tx * 4];
            ull ap[4];
            ap[0] = pack2(a4.x); ap[1] = pack2(a4.y);
            ap[2] = pack2(a4.z); ap[3] = pack2(a4.w);
            #pragma unroll
            for (int i = 0; i < 4; ++i) {
                ffma2(accL[i][0], ap[i], blp.x);
                ffma2(accL[i][1], ap[i], blp.y);
                ffma2(accR[i][0], ap[i], brp.x);
                ffma2(accR[i][1], ap[i], brp.y);
            }
        }
        __syncthreads();
    }
    float4 bl4 = *(const float4*)&bl[bn * 64 + tx * 4];
    float4 br4 = *(const float4*)&br[bn * 64 + tx * 4];
    #pragma unroll
    for (int i = 0; i < 4; ++i) {
        int gr = rowBase + ty * 4 + i;
        if (gr < M) {
            float2 l0 = unpack2(accL[i][0]);
            float2 l1 = unpack2(accL[i][1]);
            float2 r0 = unpack2(accR[i][0]);
            float2 r1 = unpack2(accR[i][1]);
            float4 ol, orr;
            ol.x  = l0.x + bl4.x; ol.y  = l0.y + bl4.y;
            ol.z  = l1.x + bl4.z; ol.w  = l1.y + bl4.w;
            orr.x = r0.x + br4.x; orr.y = r0.y + br4.y;
            orr.z = r1.x + br4.z; orr.w = r1.y + br4.w;
            long coff = (long)gr * N + bn * 64 + tx * 4;
            *(float4*)&CL[coff] = ol;
            *(float4*)&CR[coff] = orr;
        }
    }
}

// ---------------- single SGEMM (output projection), FFMA2 inner -------------
__global__ __launch_bounds__(256)
void sgemm_bias(const float* __restrict__ A, const float* __restrict__ B,
                const float* __restrict__ bias, float* __restrict__ C,
                int M, int N, int K) {
    __shared__ float As[16][64];
    __shared__ float Bs[16][64];
    int tid = threadIdx.x;
    int tx = tid & 15, ty = tid >> 4;
    int bm = blockIdx.x, bn = blockIdx.y;
    int rowBase = bm * 64;

    int aRow = tid >> 2;
    int aK   = (tid & 3) * 4;
    int bK   = tid >> 4;
    int bN   = (tid & 15) * 4;

    ull acc[4][2] = {};
    for (int k0 = 0; k0 < K; k0 += 16) {
        float4 av;
        int gr = rowBase + aRow;
        if (gr < M) av = *(const float4*)&A[(long)gr * K + k0 + aK];
        else        av = make_float4(0.f, 0.f, 0.f, 0.f);
        As[aK + 0][aRow] = av.x;
        As[aK + 1][aRow] = av.y;
        As[aK + 2][aRow] = av.z;
        As[aK + 3][aRow] = av.w;
        *(float4*)&Bs[bK][bN] = *(const float4*)&B[(long)(k0 + bK) * N + bn * 64 + bN];
        __syncthreads();
        #pragma unroll
        for (int kk = 0; kk < 16; ++kk) {
            float4 a4 = *(const float4*)&As[kk][ty * 4];
            ulonglong2 bp = *(const ulonglong2*)&Bs[kk][tx * 4];
            ull ap[4];
            ap[0] = pack2(a4.x); ap[1] = pack2(a4.y);
            ap[2] = pack2(a4.z); ap[3] = pack2(a4.w);
            #pragma unroll
            for (int i = 0; i < 4; ++i) {
                ffma2(acc[i][0], ap[i], bp.x);
                ffma2(acc[i][1], ap[i], bp.y);
            }
        }
        __syncthreads();
    }
    float4 bias4 = *(const float4*)&bias[bn * 64 + tx * 4];
    #pragma unroll
    for (int i = 0; i < 4; ++i) {
        int gr = rowBase + ty * 4 + i;
        if (gr < M) {
            float2 c0 = unpack2(acc[i][0]);
            float2 c1 = unpack2(acc[i][1]);
            float4 o;
            o.x = c0.x + bias4.x;
            o.y = c0.y + bias4.y;
            o.z = c1.x + bias4.z;
            o.w = c1.y + bias4.w;
            *(float4*)&C[(long)gr * N + bn * 64 + tx * 4] = o;
        }
    }
}

// ---------------- GATv2 edge phase: one warp per dst node ------------------
// Issue-bound. vs R13: no self check (filtered in CSR), no prefetch clamps
// (padded array), single expf per edge (w==1 exactly on the rescale path).
__global__ __launch_bounds__(256)
void gat_edge_kernel(const float* __restrict__ XL, const float* __restrict__ XR,
                     const float* __restrict__ att, const float* __restrict__ We,
                     const float* __restrict__ bias, float* __restrict__ out,
                     int applyElu) {
    int gid  = blockIdx.x * blockDim.x + threadIdx.x;
    int n    = gid >> 5;
    int lane = gid & 31;
    if (n >= NN) return;

    int base = (lane >> 3) * CH + (lane & 7) * 4;   // head*32 + chan4
    float4 xr4 = *(const float4*)&XR[n * HCC + base];
    float4 at4 = *(const float4*)&att[base];
    float4 we4 = *(const float4*)&We[base];
    ulonglong2 xr2 = *(ulonglong2*)&xr4;
    ulonglong2 we2 = *(ulonglong2*)&we4;

    float mx = -CUDART_INF_F, dn = 0.f;
    ull acc0 = 0, acc1 = 0;                         // packed 2+2 channels

    int beg = g_rowptr[n], end = g_rowptr[n + 1];

#define PROC_EDGE(ED, XLV) do {                                               \
    ulonglong2 xl2 = *(ulonglong2*)&(XLV);                                    \
    ull ae2 = pack2(__int_as_float((ED).y));                                  \
    ull m0 = fma2v(ae2, we2.x, add2(xl2.x, xr2.x));                           \
    ull m1 = fma2v(ae2, we2.y, add2(xl2.y, xr2.y));                           \
    float2 ma = unpack2(m0), mb = unpack2(m1);                                \
    float l0 = fmaxf(ma.x, 0.2f * ma.x);                                      \
    float l1 = fmaxf(ma.y, 0.2f * ma.y);                                      \
    float l2 = fmaxf(mb.x, 0.2f * mb.x);                                      \
    float l3 = fmaxf(mb.y, 0.2f * mb.y);                                      \
    float p = fmaf(l3, at4.w, fmaf(l2, at4.z, fmaf(l1, at4.y, l0 * at4.x)));  \
    p += __shfl_xor_sync(0xffffffffu, p, 4);                                  \
    p += __shfl_xor_sync(0xffffffffu, p, 2);                                  \
    p += __shfl_xor_sync(0xffffffffu, p, 1);                                  \
    if (p > mx) {                                                             \
        float r = __expf(mx - p);      /* w = expf(0) = 1 exactly */          \
        ull r2 = pack2(r);                                                    \
        dn = fmaf(dn, r, 1.f);                                                \
        acc0 = fma2v(acc0, r2, xl2.x);                                        \
        acc1 = fma2v(acc1, r2, xl2.y);                                        \
        mx = p;                                                               \
    } else {                                                                  \
        float w = __expf(p - mx);                                             \
        dn += w;                                                              \
        ull w2 = pack2(w);                                                    \
        acc0 = fma2v(w2, xl2.x, acc0);                                        \
        acc1 = fma2v(w2, xl2.y, acc1);                                        \
    }                                                                         \
} while (0)

    if (beg < end) {
        // unclamped prefetch: reads may cross into the next node's segment or
        // the zero-init pad — values discarded, indices always in-bounds.
        int2 edA = g_ecsr[beg];
        int2 edB = g_ecsr[beg + 1];
        float4 xlA = *(const float4*)&XL[(long)edA.x * HCC + base];
        int e = beg;
        while (true) {
            float4 xlB = *(const float4*)&XL[(long)edB.x * HCC + base];
            int2 edC = g_ecsr[e + 2];
            PROC_EDGE(edA, xlA);
            if (++e >= end) break;

            float4 xlC = *(const float4*)&XL[(long)edC.x * HCC + base];
            int2 edD = g_ecsr[e + 2];
            PROC_EDGE(edB, xlB);
            if (++e >= end) break;

            edA = edC; edB = edD; xlA = xlC;
        }
    }
#undef PROC_EDGE

    // self loop (always added, edge_attr = mean of incoming non-self attrs)
    {
        int   c  = g_ascnt[n];
        float la = (c > 0) ? g_asum[n] / (float)c : 0.f;
        float4 xl4 = *(const float4*)&XL[n * HCC + base];
        ulonglong2 xl2 = *(ulonglong2*)&xl4;
        ull la2 = pack2(la);
        ull m0 = fma2v(la2, we2.x, add2(xl2.x, xr2.x));
        ull m1 = fma2v(la2, we2.y, add2(xl2.y, xr2.y));
        float2 ma = unpack2(m0), mb = unpack2(m1);
        float l0 = fmaxf(ma.x, 0.2f * ma.x);
        float l1 = fmaxf(ma.y, 0.2f * ma.y);
        float l2 = fmaxf(mb.x, 0.2f * mb.x);
        float l3 = fmaxf(mb.y, 0.2f * mb.y);
        float p = fmaf(l3, at4.w, fmaf(l2, at4.z, fmaf(l1, at4.y, l0 * at4.x)));
        p += __shfl_xor_sync(0xffffffffu, p, 4);
        p += __shfl_xor_sync(0xffffffffu, p, 2);
        p += __shfl_xor_sync(0xffffffffu, p, 1);
        if (p > mx) {
            float r = __expf(mx - p);
            ull r2 = pack2(r);
            dn = fmaf(dn, r, 1.f);
            acc0 = fma2v(acc0, r2, xl2.x);
            acc1 = fma2v(acc1, r2, xl2.y);
            mx = p;
        } else {
            float w = __expf(p - mx);
            dn += w;
            ull w2 = pack2(w);
            acc0 = fma2v(w2, xl2.x, acc0);
            acc1 = fma2v(w2, xl2.y, acc1);
        }
    }

    float4 b4 = *(const float4*)&bias[base];
    float inv = 1.f / dn;
    float2 a01 = unpack2(acc0);
    float2 a23 = unpack2(acc1);
    float4 o;
    o.x = fmaf(a01.x, inv, b4.x);
    o.y = fmaf(a01.y, inv, b4.y);
    o.z = fmaf(a23.x, inv, b4.z);
    o.w = fmaf(a23.y, inv, b4.w);
    if (applyElu) {
        o.x = (o.x > 0.f) ? o.x : (__expf(o.x) - 1.f);
        o.y = (o.y > 0.f) ? o.y : (__expf(o.y) - 1.f);
        o.z = (o.z > 0.f) ? o.z : (__expf(o.z) - 1.f);
        o.w = (o.w > 0.f) ? o.w : (__expf(o.w) - 1.f);
    }
    *(float4*)&out[n * HCC + base] = o;
}

// ---------------- launch ----------------------------------------------------
extern "C" void kernel_launch(void* const* d_in, const int* in_sizes, int n_in,
                              void* d_out, int out_size) {
    const float* x     = (const float*)d_in[0];
    const int*   ei    = (const int*)d_in[1];
    const float* eattr = (const float*)d_in[2];
    const float* Wl1 = (const float*)d_in[3];
    const float* bl1 = (const float*)d_in[4];
    const float* Wr1 = (const float*)d_in[5];
    const float* br1 = (const float*)d_in[6];
    const float* We1 = (const float*)d_in[7];
    const float* att1= (const float*)d_in[8];
    const float* b1  = (const float*)d_in[9];
    const float* Wl2 = (const float*)d_in[10];
    const float* bl2 = (const float*)d_in[11];
    const float* Wr2 = (const float*)d_in[12];
    const float* br2 = (const float*)d_in[13];
    const float* We2 = (const float*)d_in[14];
    const float* att2= (const float*)d_in[15];
    const float* b2  = (const float*)d_in[16];
    const float* Wo  = (const float*)d_in[17];
    const float* bo  = (const float*)d_in[18];
    float* out = (float*)d_out;

    int E = in_sizes[1] / 2;        // 640000
    int N = in_sizes[0] / HCC;      // 20000

    float *XL, *XR, *H;
    cudaGetSymbolAddress((void**)&XL, g_XL);
    cudaGetSymbolAddress((void**)&XR, g_XR);
    cudaGetSymbolAddress((void**)&H,  g_H);

    // secondary stream + events for CSR || GEMM1 overlap
    static cudaStream_t s1 = nullptr;
    static cudaEvent_t evFork = nullptr, evJoin = nullptr;
    if (s1 == nullptr) {
        cudaStreamCreateWithFlags(&s1, cudaStreamNonBlocking);
        cudaEventCreateWithFlags(&evFork, cudaEventDisableTiming);
        cudaEventCreateWithFlags(&evJoin, cudaEventDisableTiming);
    }

    dim3 gemmGrid((N + 63) / 64, HCC / 64);
    dim3 gemmGridOut((N + 63) / 64, DOUT / 64);
    int edgeBlocks = (N * 32 + 255) / 256;       // one warp per node
    int eBlocks4   = ((E + 3) / 4 + 255) / 256;  // 4 edges per thread
    int nBlocks    = (N + 255) / 256;

    // ---- fork: CSR build on s1, layer-1 GEMM on main stream
    cudaEventRecord(evFork, 0);
    cudaStreamWaitEvent(s1, evFork, 0);

    zero_counts_kernel<<<nBlocks, 256, 0, s1>>>();
    hist_kernel<<<eBlocks4, 256, 0, s1>>>(ei, eattr, E);
    scan_kernel<<<1, 1024, 0, s1>>>(N);
    scatter_kernel<<<eBlocks4, 256, 0, s1>>>(ei, eattr, E);
    cudaEventRecord(evJoin, s1);

    sgemm_dual_bias<<<gemmGrid, 256>>>(x, Wl1, Wr1, bl1, br1, XL, XR, N, HCC, HCC);

    cudaStreamWaitEvent(0, evJoin, 0);

    // layer 1 edge phase
    gat_edge_kernel<<<edgeBlocks, 256>>>(XL, XR, att1, We1, b1, H, 1);

    // layer 2
    sgemm_dual_bias<<<gemmGrid, 256>>>(H, Wl2, Wr2, bl2, br2, XL, XR, N, HCC, HCC);
    gat_edge_kernel<<<edgeBlocks, 256>>>(XL, XR, att2, We2, b2, H, 1);

    // output projection
    sgemm_bias<<<gemmGridOut, 256>>>(H, Wo, bo, out, N, DOUT, HCC);
}

// round 15
// speedup vs baseline: 1.3760x; 1.0170x over previous
#include <cuda_runtime.h>
#include <math_constants.h>

// Problem constants (fixed by the dataset)
#define NN   20000      // nodes
#define EE   640000     // edges
#define HCC  128        // H * C
#define NH   4          // heads
#define CH   32         // channels per head
#define DOUT 64

// ---------------- device scratch (static: no allocations allowed) -----------
__device__ float g_XL[NN * HCC];
__device__ float g_XR[NN * HCC];
__device__ float g_H [NN * HCC];
__device__ int   g_cnt[NN];
__device__ int   g_cur[NN];
__device__ float g_asum[NN];        // sum of non-self incoming edge_attr
__device__ int   g_rowptr[NN + 1];
__device__ int2  g_ecsr[EE + 16];   // non-self edges, CSR by dst; zero-init pad
                                    // (lets the edge kernel prefetch unclamped)

// ---------------- packed fp32x2 helpers (Blackwell, compile-proven) ---------
typedef unsigned long long ull;
__device__ __forceinline__ void ffma2(ull& d, ull a, ull b) {
    asm("fma.rn.f32x2 %0, %1, %2, %0;" : "+l"(d) : "l"(a), "l"(b));
}
__device__ __forceinline__ ull fma2v(ull a, ull b, ull c) {
    ull d;
    asm("fma.rn.f32x2 %0, %1, %2, %3;" : "=l"(d) : "l"(a), "l"(b), "l"(c));
    return d;
}
__device__ __forceinline__ ull add2(ull a, ull b) {
    ull d;
    asm("add.rn.f32x2 %0, %1, %2;" : "=l"(d) : "l"(a), "l"(b));
    return d;
}
__device__ __forceinline__ ull mul2(ull a, ull b) {
    ull d;
    asm("mul.rn.f32x2 %0, %1, %2;" : "=l"(d) : "l"(a), "l"(b));
    return d;
}
__device__ __forceinline__ ull pack2(float x) {
    ull r;
    asm("mov.b64 %0, {%1, %1};" : "=l"(r) : "f"(x));
    return r;
}
__device__ __forceinline__ float2 unpack2(ull v) {
    float2 o;
    asm("mov.b64 {%0, %1}, %2;" : "=f"(o.x), "=f"(o.y) : "l"(v));
    return o;
}

// ---------------- CSR build (self-edges filtered out here) ------------------
__global__ void zero_counts_kernel() {
    int i = blockIdx.x * blockDim.x + threadIdx.x;
    if (i < NN) { g_cnt[i] = 0; g_cur[i] = 0; g_asum[i] = 0.f; }
}

// histogram (non-self only) + per-dst attr sum; 4-batched loads for MLP
__global__ void hist_kernel(const int* __restrict__ ei,
                            const float* __restrict__ eattr, int E) {
    int T = gridDim.x * blockDim.x;
    int t = blockIdx.x * blockDim.x + threadIdx.x;
    int   s[4], d[4];
    float a[4];
    bool  v[4];
    #pragma unroll
    for (int j = 0; j < 4; ++j) {
        int e = t + j * T;
        v[j] = (e < E);
        int ec = v[j] ? e : 0;
        s[j] = ei[ec];
        d[j] = ei[E + ec];
        a[j] = eattr[ec];
    }
    #pragma unroll
    for (int j = 0; j < 4; ++j) {
        if (!v[j] || d[j] < 0 || d[j] >= NN || s[j] == d[j]) continue;
        atomicAdd(&g_cnt[d[j]], 1);
        atomicAdd(&g_asum[d[j]], a[j]);
    }
}

// single-block exclusive scan of g_cnt -> g_rowptr
__global__ void scan_kernel(int n) {
    __shared__ int sums[1024];
    int tid = threadIdx.x;
    int per = (n + 1023) >> 10;
    int beg = tid * per;
    int end = beg + per;
    if (beg > n) beg = n;
    if (end > n) end = n;
    int s = 0;
    for (int i = beg; i < end; ++i) s += g_cnt[i];
    sums[tid] = s;
    __syncthreads();
    for (int off = 1; off < 1024; off <<= 1) {
        int v = (tid >= off) ? sums[tid - off] : 0;
        __syncthreads();
        sums[tid] += v;
        __syncthreads();
    }
    int run = (tid == 0) ? 0 : sums[tid - 1];
    for (int i = beg; i < end; ++i) { g_rowptr[i] = run; run += g_cnt[i]; }
    if (tid == 0) g_rowptr[n] = sums[1023];
}

// scatter (non-self only); 4-batched loads
__global__ void scatter_kernel(const int* __restrict__ ei,
                               const float* __restrict__ eattr, int E) {
    int T = gridDim.x * blockDim.x;
    int t = blockIdx.x * blockDim.x + threadIdx.x;
    int   s[4], d[4];
    float a[4];
    bool  v[4];
    #pragma unroll
    for (int j = 0; j < 4; ++j) {
        int e = t + j * T;
        v[j] = (e < E);
        int ec = v[j] ? e : 0;
        s[j] = ei[ec];
        d[j] = ei[E + ec];
        a[j] = eattr[ec];
    }
    #pragma unroll
    for (int j = 0; j < 4; ++j) {
        if (!v[j] || d[j] < 0 || d[j] >= NN || s[j] == d[j]) continue;
        int pos = g_rowptr[d[j]] + atomicAdd(&g_cur[d[j]], 1);
        g_ecsr[pos] = make_int2(s[j], __float_as_int(a[j]));
    }
}

// ---------------- fused dual SGEMM (FFMA2 inner, known good) ----------------
__global__ __launch_bounds__(256)
void sgemm_dual_bias(const float* __restrict__ A,
                     const float* __restrict__ Bl, const float* __restrict__ Br,
                     const float* __restrict__ bl, const float* __restrict__ br,
                     float* __restrict__ CL, float* __restrict__ CR,
                     int M, int N, int K) {
    __shared__ float As [16][64];
    __shared__ float Bls[16][64];
    __shared__ float Brs[16][64];
    int tid = threadIdx.x;
    int tx = tid & 15, ty = tid >> 4;
    int bm = blockIdx.x, bn = blockIdx.y;
    int rowBase = bm * 64;

    int aRow = tid >> 2;
    int aK   = (tid & 3) * 4;
    int bK   = tid >> 4;
    int bN   = (tid & 15) * 4;

    ull accL[4][2] = {};
    ull accR[4][2] = {};

    for (int k0 = 0; k0 < K; k0 += 16) {
        float4 av;
        int gr = rowBase + aRow;
        if (gr < M) av = *(const float4*)&A[(long)gr * K + k0 + aK];
        else        av = make_float4(0.f, 0.f, 0.f, 0.f);
        As[aK + 0][aRow] = av.x;
        As[aK + 1][aRow] = av.y;
        As[aK + 2][aRow] = av.z;
        As[aK + 3][aRow] = av.w;
        long boff = (long)(k0 + bK) * N + bn * 64 + bN;
        *(float4*)&Bls[bK][bN] = *(const float4*)&Bl[boff];
        *(float4*)&Brs[bK][bN] = *(const float4*)&Br[boff];
        __syncthreads();
        #pragma unroll
        for (int kk = 0; kk < 16; ++kk) {
            float4 a4 = *(const float4*)&As[kk][ty * 4];
            ulonglong2 blp = *(const ulonglong2*)&Bls[kk][tx * 4];
            ulonglong2 brp = *(const ulonglong2*)&Brs[kk][tx * 4];
            ull ap[4];
            ap[0] = pack2(a4.x); ap[1] = pack2(a4.y);
            ap[2] = pack2(a4.z); ap[3] = pack2(a4.w);
            #pragma unroll
            for (int i = 0; i < 4; ++i) {
                ffma2(accL[i][0], ap[i], blp.x);
                ffma2(accL[i][1], ap[i], blp.y);
                ffma2(accR[i][0], ap[i], brp.x);
                ffma2(accR[i][1], ap[i], brp.y);
            }
        }
        __syncthreads();
    }
    float4 bl4 = *(const float4*)&bl[bn * 64 + tx * 4];
    float4 br4 = *(const float4*)&br[bn * 64 + tx * 4];
    #pragma unroll
    for (int i = 0; i < 4; ++i) {
        int gr = rowBase + ty * 4 + i;
        if (gr < M) {
            float2 l0 = unpack2(accL[i][0]);
            float2 l1 = unpack2(accL[i][1]);
            float2 r0 = unpack2(accR[i][0]);
            float2 r1 = unpack2(accR[i][1]);
            float4 ol, orr;
            ol.x  = l0.x + bl4.x; ol.y  = l0.y + bl4.y;
            ol.z  = l1.x + bl4.z; ol.w  = l1.y + bl4.w;
            orr.x = r0.x + br4.x; orr.y = r0.y + br4.y;
            orr.z = r1.x + br4.z; orr.w = r1.y + br4.w;
            long coff = (long)gr * N + bn * 64 + tx * 4;
            *(float4*)&CL[coff] = ol;
            *(float4*)&CR[coff] = orr;
        }
    }
}

// ---------------- single SGEMM (output projection), FFMA2 inner -------------
__global__ __launch_bounds__(256)
void sgemm_bias(const float* __restrict__ A, const float* __restrict__ B,
                const float* __restrict__ bias, float* __restrict__ C,
                int M, int N, int K) {
    __shared__ float As[16][64];
    __shared__ float Bs[16][64];
    int tid = threadIdx.x;
    int tx = tid & 15, ty = tid >> 4;
    int bm = blockIdx.x, bn = blockIdx.y;
    int rowBase = bm * 64;

    int aRow = tid >> 2;
    int aK   = (tid & 3) * 4;
    int bK   = tid >> 4;
    int bN   = (tid & 15) * 4;

    ull acc[4][2] = {};
    for (int k0 = 0; k0 < K; k0 += 16) {
        float4 av;
        int gr = rowBase + aRow;
        if (gr < M) av = *(const float4*)&A[(long)gr * K + k0 + aK];
        else        av = make_float4(0.f, 0.f, 0.f, 0.f);
        As[aK + 0][aRow] = av.x;
        As[aK + 1][aRow] = av.y;
        As[aK + 2][aRow] = av.z;
        As[aK + 3][aRow] = av.w;
        *(float4*)&Bs[bK][bN] = *(const float4*)&B[(long)(k0 + bK) * N + bn * 64 + bN];
        __syncthreads();
        #pragma unroll
        for (int kk = 0; kk < 16; ++kk) {
            float4 a4 = *(const float4*)&As[kk][ty * 4];
            ulonglong2 bp = *(const ulonglong2*)&Bs[kk][tx * 4];
            ull ap[4];
            ap[0] = pack2(a4.x); ap[1] = pack2(a4.y);
            ap[2] = pack2(a4.z); ap[3] = pack2(a4.w);
            #pragma unroll
            for (int i = 0; i < 4; ++i) {
                ffma2(acc[i][0], ap[i], bp.x);
                ffma2(acc[i][1], ap[i], bp.y);
            }
        }
        __syncthreads();
    }
    float4 bias4 = *(const float4*)&bias[bn * 64 + tx * 4];
    #pragma unroll
    for (int i = 0; i < 4; ++i) {
        int gr = rowBase + ty * 4 + i;
        if (gr < M) {
            float2 c0 = unpack2(acc[i][0]);
            float2 c1 = unpack2(acc[i][1]);
            float4 o;
            o.x = c0.x + bias4.x;
            o.y = c0.y + bias4.y;
            o.z = c1.x + bias4.z;
            o.w = c1.y + bias4.w;
            *(float4*)&C[(long)gr * N + bn * 64 + tx * 4] = o;
        }
    }
}

// ---------------- GATv2 edge phase: one warp per dst node ------------------
// Group-of-4 edges: 4 independent dot products, interleaved shuffle rounds
// (4 latency chains overlap), group-max online softmax (1 rescale per group),
// ping-pong double buffering (no shift moves). Tail edges get p = -inf.
__global__ __launch_bounds__(256)
void gat_edge_kernel(const float* __restrict__ XL, const float* __restrict__ XR,
                     const float* __restrict__ att, const float* __restrict__ We,
                     const float* __restrict__ bias, float* __restrict__ out,
                     int applyElu) {
    int gid  = blockIdx.x * blockDim.x + threadIdx.x;
    int n    = gid >> 5;
    int lane = gid & 31;
    if (n >= NN) return;

    int base = (lane >> 3) * CH + (lane & 7) * 4;   // head*32 + chan4
    float4 xr4 = *(const float4*)&XR[n * HCC + base];
    float4 at4 = *(const float4*)&att[base];
    float4 we4 = *(const float4*)&We[base];
    ulonglong2 xr2 = *(ulonglong2*)&xr4;
    ulonglong2 we2 = *(ulonglong2*)&we4;

    float mx = -CUDART_INF_F, dn = 0.f;
    ull acc0 = 0, acc1 = 0;                         // packed 2+2 channels

    int beg = g_rowptr[n], end = g_rowptr[n + 1];

#define LOAD_GROUP(E0, ED, XLV) do {                                          \
    _Pragma("unroll")                                                         \
    for (int j = 0; j < 4; ++j) (ED)[j] = g_ecsr[(E0) + j];                   \
    _Pragma("unroll")                                                         \
    for (int j = 0; j < 4; ++j)                                               \
        (XLV)[j] = *(const float4*)&XL[(long)(ED)[j].x * HCC + base];         \
} while (0)

#define PROC_GROUP(E0, ED, XLV) do {                                          \
    float p[4];                                                               \
    _Pragma("unroll")                                                         \
    for (int j = 0; j < 4; ++j) {                                             \
        ulonglong2 xl2 = *(ulonglong2*)&(XLV)[j];                             \
        ull ae2 = pack2(__int_as_float((ED)[j].y));                           \
        ull m0 = fma2v(ae2, we2.x, add2(xl2.x, xr2.x));                       \
        ull m1 = fma2v(ae2, we2.y, add2(xl2.y, xr2.y));                       \
        float2 ma = unpack2(m0), mb = unpack2(m1);                            \
        float l0 = fmaxf(ma.x, 0.2f * ma.x);                                  \
        float l1 = fmaxf(ma.y, 0.2f * ma.y);                                  \
        float l2 = fmaxf(mb.x, 0.2f * mb.x);                                  \
        float l3 = fmaxf(mb.y, 0.2f * mb.y);                                  \
        p[j] = fmaf(l3, at4.w, fmaf(l2, at4.z, fmaf(l1, at4.y, l0 * at4.x))); \
    }                                                                         \
    _Pragma("unroll")                                                         \
    for (int j = 0; j < 4; ++j) p[j] += __shfl_xor_sync(0xffffffffu, p[j], 4);\
    _Pragma("unroll")                                                         \
    for (int j = 0; j < 4; ++j) p[j] += __shfl_xor_sync(0xffffffffu, p[j], 2);\
    _Pragma("unroll")                                                         \
    for (int j = 0; j < 4; ++j) p[j] += __shfl_xor_sync(0xffffffffu, p[j], 1);\
    _Pragma("unroll")                                                         \
    for (int j = 0; j < 4; ++j)                                               \
        if ((E0) + j >= end) p[j] = -CUDART_INF_F;                            \
    float gm = fmaxf(fmaxf(p[0], p[1]), fmaxf(p[2], p[3]));                   \
    if (gm > mx) {                                                            \
        float r = __expf(mx - gm);      /* exp(-inf)=0 first time */          \
        ull r2 = pack2(r);                                                    \
        dn *= r;                                                              \
        acc0 = mul2(acc0, r2);                                                \
        acc1 = mul2(acc1, r2);                                                \
        mx = gm;                                                              \
    }                                                                         \
    _Pragma("unroll")                                                         \
    for (int j = 0; j < 4; ++j) {                                             \
        float w = __expf(p[j] - mx);   /* 0 for tail edges */                 \
        dn += w;                                                              \
        ull w2 = pack2(w);                                                    \
        ulonglong2 xl2 = *(ulonglong2*)&(XLV)[j];                             \
        acc0 = fma2v(w2, xl2.x, acc0);                                        \
        acc1 = fma2v(w2, xl2.y, acc1);                                        \
    }                                                                         \
} while (0)

    if (beg < end) {
        int2   edA[4], edB[4];
        float4 xlA[4], xlB[4];
        LOAD_GROUP(beg, edA, xlA);
        int e = beg;
        while (true) {
            LOAD_GROUP(e + 4, edB, xlB);    // prefetch (pad-safe, unclamped)
            PROC_GROUP(e, edA, xlA);
            e += 4;
            if (e >= end) break;
            LOAD_GROUP(e + 4, edA, xlA);
            PROC_GROUP(e, edB, xlB);
            e += 4;
            if (e >= end) break;
        }
    }
#undef LOAD_GROUP
#undef PROC_GROUP

    // self loop (always added, edge_attr = mean of incoming non-self attrs)
    {
        int   c  = end - beg;               // == non-self incoming count
        float la = (c > 0) ? g_asum[n] / (float)c : 0.f;
        float4 xl4 = *(const float4*)&XL[n * HCC + base];
        ulonglong2 xl2 = *(ulonglong2*)&xl4;
        ull la2 = pack2(la);
        ull m0 = fma2v(la2, we2.x, add2(xl2.x, xr2.x));
        ull m1 = fma2v(la2, we2.y, add2(xl2.y, xr2.y));
        float2 ma = unpack2(m0), mb = unpack2(m1);
        float l0 = fmaxf(ma.x, 0.2f * ma.x);
        float l1 = fmaxf(ma.y, 0.2f * ma.y);
        float l2 = fmaxf(mb.x, 0.2f * mb.x);
        float l3 = fmaxf(mb.y, 0.2f * mb.y);
        float p = fmaf(l3, at4.w, fmaf(l2, at4.z, fmaf(l1, at4.y, l0 * at4.x)));
        p += __shfl_xor_sync(0xffffffffu, p, 4);
        p += __shfl_xor_sync(0xffffffffu, p, 2);
        p += __shfl_xor_sync(0xffffffffu, p, 1);
        if (p > mx) {
            float r = __expf(mx - p);
            ull r2 = pack2(r);
            dn = fmaf(dn, r, 1.f);          // w = exp(0) = 1 exactly
            acc0 = fma2v(acc0, r2, xl2.x);
            acc1 = fma2v(acc1, r2, xl2.y);
            mx = p;
        } else {
            float w = __expf(p - mx);
            dn += w;
            ull w2 = pack2(w);
            acc0 = fma2v(w2, xl2.x, acc0);
            acc1 = fma2v(w2, xl2.y, acc1);
        }
    }

    float4 b4 = *(const float4*)&bias[base];
    float inv = 1.f / dn;
    float2 a01 = unpack2(acc0);
    float2 a23 = unpack2(acc1);
    float4 o;
    o.x = fmaf(a01.x, inv, b4.x);
    o.y = fmaf(a01.y, inv, b4.y);
    o.z = fmaf(a23.x, inv, b4.z);
    o.w = fmaf(a23.y, inv, b4.w);
    if (applyElu) {
        o.x = (o.x > 0.f) ? o.x : (__expf(o.x) - 1.f);
        o.y = (o.y > 0.f) ? o.y : (__expf(o.y) - 1.f);
        o.z = (o.z > 0.f) ? o.z : (__expf(o.z) - 1.f);
        o.w = (o.w > 0.f) ? o.w : (__expf(o.w) - 1.f);
    }
    *(float4*)&out[n * HCC + base] = o;
}

// ---------------- launch ----------------------------------------------------
extern "C" void kernel_launch(void* const* d_in, const int* in_sizes, int n_in,
                              void* d_out, int out_size) {
    const float* x     = (const float*)d_in[0];
    const int*   ei    = (const int*)d_in[1];
    const float* eattr = (const float*)d_in[2];
    const float* Wl1 = (const float*)d_in[3];
    const float* bl1 = (const float*)d_in[4];
    const float* Wr1 = (const float*)d_in[5];
    const float* br1 = (const float*)d_in[6];
    const float* We1 = (const float*)d_in[7];
    const float* att1= (const float*)d_in[8];
    const float* b1  = (const float*)d_in[9];
    const float* Wl2 = (const float*)d_in[10];
    const float* bl2 = (const float*)d_in[11];
    const float* Wr2 = (const float*)d_in[12];
    const float* br2 = (const float*)d_in[13];
    const float* We2 = (const float*)d_in[14];
    const float* att2= (const float*)d_in[15];
    const float* b2  = (const float*)d_in[16];
    const float* Wo  = (const float*)d_in[17];
    const float* bo  = (const float*)d_in[18];
    float* out = (float*)d_out;

    int E = in_sizes[1] / 2;        // 640000
    int N = in_sizes[0] / HCC;      // 20000

    float *XL, *XR, *H;
    cudaGetSymbolAddress((void**)&XL, g_XL);
    cudaGetSymbolAddress((void**)&XR, g_XR);
    cudaGetSymbolAddress((void**)&H,  g_H);

    // secondary stream + events for CSR || GEMM1 overlap
    static cudaStream_t s1 = nullptr;
    static cudaEvent_t evFork = nullptr, evJoin = nullptr;
    if (s1 == nullptr) {
        cudaStreamCreateWithFlags(&s1, cudaStreamNonBlocking);
        cudaEventCreateWithFlags(&evFork, cudaEventDisableTiming);
        cudaEventCreateWithFlags(&evJoin, cudaEventDisableTiming);
    }

    dim3 gemmGrid((N + 63) / 64, HCC / 64);
    dim3 gemmGridOut((N + 63) / 64, DOUT / 64);
    int edgeBlocks = (N * 32 + 255) / 256;       // one warp per node
    int eBlocks4   = ((E + 3) / 4 + 255) / 256;  // 4 edges per thread
    int nBlocks    = (N + 255) / 256;

    // ---- fork: CSR build on s1, layer-1 GEMM on main stream
    cudaEventRecord(evFork, 0);
    cudaStreamWaitEvent(s1, evFork, 0);

    zero_counts_kernel<<<nBlocks, 256, 0, s1>>>();
    hist_kernel<<<eBlocks4, 256, 0, s1>>>(ei, eattr, E);
    scan_kernel<<<1, 1024, 0, s1>>>(N);
    scatter_kernel<<<eBlocks4, 256, 0, s1>>>(ei, eattr, E);
    cudaEventRecord(evJoin, s1);

    sgemm_dual_bias<<<gemmGrid, 256>>>(x, Wl1, Wr1, bl1, br1, XL, XR, N, HCC, HCC);

    cudaStreamWaitEvent(0, evJoin, 0);

    // layer 1 edge phase
    gat_edge_kernel<<<edgeBlocks, 256>>>(XL, XR, att1, We1, b1, H, 1);

    // layer 2
    sgemm_dual_bias<<<gemmGrid, 256>>>(H, Wl2, Wr2, bl2, br2, XL, XR, N, HCC, HCC);
    gat_edge_kernel<<<edgeBlocks, 256>>>(XL, XR, att2, We2, b2, H, 1);

    // output projection
    sgemm_bias<<<gemmGridOut, 256>>>(H, Wo, bo, out, N, DOUT, HCC);
}

// round 16
// speedup vs baseline: 1.4267x; 1.0368x over previous
#include <cuda_runtime.h>
#include <math_constants.h>

// Problem constants (fixed by the dataset)
#define NN   20000      // nodes
#define EE   640000     // edges
#define HCC  128        // H * C
#define NH   4          // heads
#define CH   32         // channels per head
#define DOUT 64

// ---------------- device scratch (static: no allocations allowed) -----------
__device__ float g_XL[NN * HCC];
__device__ float g_XR[NN * HCC];
__device__ float g_H [NN * HCC];
__device__ int   g_cnt[NN];
__device__ int   g_cur[NN];
__device__ int   g_rowptr[NN + 1];
__device__ int2  g_ecsr[EE + 16];   // non-self edges, CSR by dst; zero-init pad
                                    // (lets the edge kernel prefetch unclamped)

// ---------------- packed fp32x2 helpers (Blackwell, compile-proven) ---------
typedef unsigned long long ull;
__device__ __forceinline__ void ffma2(ull& d, ull a, ull b) {
    asm("fma.rn.f32x2 %0, %1, %2, %0;" : "+l"(d) : "l"(a), "l"(b));
}
__device__ __forceinline__ ull fma2v(ull a, ull b, ull c) {
    ull d;
    asm("fma.rn.f32x2 %0, %1, %2, %3;" : "=l"(d) : "l"(a), "l"(b), "l"(c));
    return d;
}
__device__ __forceinline__ ull add2(ull a, ull b) {
    ull d;
    asm("add.rn.f32x2 %0, %1, %2;" : "=l"(d) : "l"(a), "l"(b));
    return d;
}
__device__ __forceinline__ ull pack2(float x) {
    ull r;
    asm("mov.b64 %0, {%1, %1};" : "=l"(r) : "f"(x));
    return r;
}
__device__ __forceinline__ float2 unpack2(ull v) {
    float2 o;
    asm("mov.b64 {%0, %1}, %2;" : "=f"(o.x), "=f"(o.y) : "l"(v));
    return o;
}

// ---------------- CSR build (self-edges filtered out here) ------------------
__global__ void zero_counts_kernel() {
    int i = blockIdx.x * blockDim.x + threadIdx.x;
    if (i < NN) { g_cnt[i] = 0; g_cur[i] = 0; }
}

// histogram (non-self only); single atomic per edge; 4-batched loads for MLP
__global__ void hist_kernel(const int* __restrict__ ei, int E) {
    int T = gridDim.x * blockDim.x;
    int t = blockIdx.x * blockDim.x + threadIdx.x;
    int s[4], d[4];
    bool v[4];
    #pragma unroll
    for (int j = 0; j < 4; ++j) {
        int e = t + j * T;
        v[j] = (e < E);
        int ec = v[j] ? e : 0;
        s[j] = ei[ec];
        d[j] = ei[E + ec];
    }
    #pragma unroll
    for (int j = 0; j < 4; ++j) {
        if (!v[j] || d[j] < 0 || d[j] >= NN || s[j] == d[j]) continue;
        atomicAdd(&g_cnt[d[j]], 1);
    }
}

// single-block exclusive scan of g_cnt -> g_rowptr
__global__ void scan_kernel(int n) {
    __shared__ int sums[1024];
    int tid = threadIdx.x;
    int per = (n + 1023) >> 10;
    int beg = tid * per;
    int end = beg + per;
    if (beg > n) beg = n;
    if (end > n) end = n;
    int s = 0;
    for (int i = beg; i < end; ++i) s += g_cnt[i];
    sums[tid] = s;
    __syncthreads();
    for (int off = 1; off < 1024; off <<= 1) {
        int v = (tid >= off) ? sums[tid - off] : 0;
        __syncthreads();
        sums[tid] += v;
        __syncthreads();
    }
    int run = (tid == 0) ? 0 : sums[tid - 1];
    for (int i = beg; i < end; ++i) { g_rowptr[i] = run; run += g_cnt[i]; }
    if (tid == 0) g_rowptr[n] = sums[1023];
}

// scatter (non-self only); 4-batched loads
__global__ void scatter_kernel(const int* __restrict__ ei,
                               const float* __restrict__ eattr, int E) {
    int T = gridDim.x * blockDim.x;
    int t = blockIdx.x * blockDim.x + threadIdx.x;
    int   s[4], d[4];
    float a[4];
    bool  v[4];
    #pragma unroll
    for (int j = 0; j < 4; ++j) {
        int e = t + j * T;
        v[j] = (e < E);
        int ec = v[j] ? e : 0;
        s[j] = ei[ec];
        d[j] = ei[E + ec];
        a[j] = eattr[ec];
    }
    #pragma unroll
    for (int j = 0; j < 4; ++j) {
        if (!v[j] || d[j] < 0 || d[j] >= NN || s[j] == d[j]) continue;
        int pos = g_rowptr[d[j]] + atomicAdd(&g_cur[d[j]], 1);
        g_ecsr[pos] = make_int2(s[j], __float_as_int(a[j]));
    }
}

// ---------------- fused dual SGEMM (FFMA2 inner, known good) ----------------
__global__ __launch_bounds__(256)
void sgemm_dual_bias(const float* __restrict__ A,
                     const float* __restrict__ Bl, const float* __restrict__ Br,
                     const float* __restrict__ bl, const float* __restrict__ br,
                     float* __restrict__ CL, float* __restrict__ CR,
                     int M, int N, int K) {
    __shared__ float As [16][64];
    __shared__ float Bls[16][64];
    __shared__ float Brs[16][64];
    int tid = threadIdx.x;
    int tx = tid & 15, ty = tid >> 4;
    int bm = blockIdx.x, bn = blockIdx.y;
    int rowBase = bm * 64;

    int aRow = tid >> 2;
    int aK   = (tid & 3) * 4;
    int bK   = tid >> 4;
    int bN   = (tid & 15) * 4;

    ull accL[4][2] = {};
    ull accR[4][2] = {};

    for (int k0 = 0; k0 < K; k0 += 16) {
        float4 av;
        int gr = rowBase + aRow;
        if (gr < M) av = *(const float4*)&A[(long)gr * K + k0 + aK];
        else        av = make_float4(0.f, 0.f, 0.f, 0.f);
        As[aK + 0][aRow] = av.x;
        As[aK + 1][aRow] = av.y;
        As[aK + 2][aRow] = av.z;
        As[aK + 3][aRow] = av.w;
        long boff = (long)(k0 + bK) * N + bn * 64 + bN;
        *(float4*)&Bls[bK][bN] = *(const float4*)&Bl[boff];
        *(float4*)&Brs[bK][bN] = *(const float4*)&Br[boff];
        __syncthreads();
        #pragma unroll
        for (int kk = 0; kk < 16; ++kk) {
            float4 a4 = *(const float4*)&As[kk][ty * 4];
            ulonglong2 blp = *(const ulonglong2*)&Bls[kk][tx * 4];
            ulonglong2 brp = *(const ulonglong2*)&Brs[kk][tx * 4];
            ull ap[4];
            ap[0] = pack2(a4.x); ap[1] = pack2(a4.y);
            ap[2] = pack2(a4.z); ap[3] = pack2(a4.w);
            #pragma unroll
            for (int i = 0; i < 4; ++i) {
                ffma2(accL[i][0], ap[i], blp.x);
                ffma2(accL[i][1], ap[i], blp.y);
                ffma2(accR[i][0], ap[i], brp.x);
                ffma2(accR[i][1], ap[i], brp.y);
            }
        }
        __syncthreads();
    }
    float4 bl4 = *(const float4*)&bl[bn * 64 + tx * 4];
    float4 br4 = *(const float4*)&br[bn * 64 + tx * 4];
    #pragma unroll
    for (int i = 0; i < 4; ++i) {
        int gr = rowBase + ty * 4 + i;
        if (gr < M) {
            float2 l0 = unpack2(accL[i][0]);
            float2 l1 = unpack2(accL[i][1]);
            float2 r0 = unpack2(accR[i][0]);
            float2 r1 = unpack2(accR[i][1]);
            float4 ol, orr;
            ol.x  = l0.x + bl4.x; ol.y  = l0.y + bl4.y;
            ol.z  = l1.x + bl4.z; ol.w  = l1.y + bl4.w;
            orr.x = r0.x + br4.x; orr.y = r0.y + br4.y;
            orr.z = r1.x + br4.z; orr.w = r1.y + br4.w;
            long coff = (long)gr * N + bn * 64 + tx * 4;
            *(float4*)&CL[coff] = ol;
            *(float4*)&CR[coff] = orr;
        }
    }
}

// ---------------- single SGEMM (output projection), FFMA2 inner -------------
__global__ __launch_bounds__(256)
void sgemm_bias(const float* __restrict__ A, const float* __restrict__ B,
                const float* __restrict__ bias, float* __restrict__ C,
                int M, int N, int K) {
    __shared__ float As[16][64];
    __shared__ float Bs[16][64];
    int tid = threadIdx.x;
    int tx = tid & 15, ty = tid >> 4;
    int bm = blockIdx.x, bn = blockIdx.y;
    int rowBase = bm * 64;

    int aRow = tid >> 2;
    int aK   = (tid & 3) * 4;
    int bK   = tid >> 4;
    int bN   = (tid & 15) * 4;

    ull acc[4][2] = {};
    for (int k0 = 0; k0 < K; k0 += 16) {
        float4 av;
        int gr = rowBase + aRow;
        if (gr < M) av = *(const float4*)&A[(long)gr * K + k0 + aK];
        else        av = make_float4(0.f, 0.f, 0.f, 0.f);
        As[aK + 0][aRow] = av.x;
        As[aK + 1][aRow] = av.y;
        As[aK + 2][aRow] = av.z;
        As[aK + 3][aRow] = av.w;
        *(float4*)&Bs[bK][bN] = *(const float4*)&B[(long)(k0 + bK) * N + bn * 64 + bN];
        __syncthreads();
        #pragma unroll
        for (int kk = 0; kk < 16; ++kk) {
            float4 a4 = *(const float4*)&As[kk][ty * 4];
            ulonglong2 bp = *(const ulonglong2*)&Bs[kk][tx * 4];
            ull ap[4];
            ap[0] = pack2(a4.x); ap[1] = pack2(a4.y);
            ap[2] = pack2(a4.z); ap[3] = pack2(a4.w);
            #pragma unroll
            for (int i = 0; i < 4; ++i) {
                ffma2(acc[i][0], ap[i], bp.x);
                ffma2(acc[i][1], ap[i], bp.y);
            }
        }
        __syncthreads();
    }
    float4 bias4 = *(const float4*)&bias[bn * 64 + tx * 4];
    #pragma unroll
    for (int i = 0; i < 4; ++i) {
        int gr = rowBase + ty * 4 + i;
        if (gr < M) {
            float2 c0 = unpack2(acc[i][0]);
            float2 c1 = unpack2(acc[i][1]);
            float4 o;
            o.x = c0.x + bias4.x;
            o.y = c0.y + bias4.y;
            o.z = c1.x + bias4.z;
            o.w = c1.y + bias4.w;
            *(float4*)&C[(long)gr * N + bn * 64 + tx * 4] = o;
        }
    }
}

// ---------------- GATv2 edge phase: one warp per dst node ------------------
// Group-of-4, no-max softmax (range-analyzed safe: |p| << 88), loop-attr mean
// accumulated in-loop (masked on tails), self-loop processed after the loop.
__global__ __launch_bounds__(256)
void gat_edge_kernel(const float* __restrict__ XL, const float* __restrict__ XR,
                     const float* __restrict__ att, const float* __restrict__ We,
                     const float* __restrict__ bias, float* __restrict__ out,
                     int applyElu) {
    int gid  = blockIdx.x * blockDim.x + threadIdx.x;
    int n    = gid >> 5;
    int lane = gid & 31;
    if (n >= NN) return;

    int base = (lane >> 3) * CH + (lane & 7) * 4;   // head*32 + chan4
    float4 xr4 = *(const float4*)&XR[n * HCC + base];
    float4 at4 = *(const float4*)&att[base];
    float4 we4 = *(const float4*)&We[base];
    ulonglong2 xr2 = *(ulonglong2*)&xr4;
    ulonglong2 we2 = *(ulonglong2*)&we4;

    float dn = 0.f, sattr = 0.f;
    ull acc0 = 0, acc1 = 0;                         // packed 2+2 channels

    int beg = g_rowptr[n], end = g_rowptr[n + 1];

#define LOAD_GROUP(E0, ED, XLV) do {                                          \
    _Pragma("unroll")                                                         \
    for (int j = 0; j < 4; ++j) (ED)[j] = g_ecsr[(E0) + j];                   \
    _Pragma("unroll")                                                         \
    for (int j = 0; j < 4; ++j)                                               \
        (XLV)[j] = *(const float4*)&XL[(long)(ED)[j].x * HCC + base];         \
} while (0)

#define PROC_GROUP(E0, ED, XLV) do {                                          \
    float p[4];                                                               \
    _Pragma("unroll")                                                         \
    for (int j = 0; j < 4; ++j) {                                             \
        ulonglong2 xl2 = *(ulonglong2*)&(XLV)[j];                             \
        ull ae2 = pack2(__int_as_float((ED)[j].y));                           \
        ull m0 = fma2v(ae2, we2.x, add2(xl2.x, xr2.x));                       \
        ull m1 = fma2v(ae2, we2.y, add2(xl2.y, xr2.y));                       \
        float2 ma = unpack2(m0), mb = unpack2(m1);                            \
        float l0 = fmaxf(ma.x, 0.2f * ma.x);                                  \
        float l1 = fmaxf(ma.y, 0.2f * ma.y);                                  \
        float l2 = fmaxf(mb.x, 0.2f * mb.x);                                  \
        float l3 = fmaxf(mb.y, 0.2f * mb.y);                                  \
        p[j] = fmaf(l3, at4.w, fmaf(l2, at4.z, fmaf(l1, at4.y, l0 * at4.x))); \
    }                                                                         \
    _Pragma("unroll")                                                         \
    for (int j = 0; j < 4; ++j) p[j] += __shfl_xor_sync(0xffffffffu, p[j], 4);\
    _Pragma("unroll")                                                         \
    for (int j = 0; j < 4; ++j) p[j] += __shfl_xor_sync(0xffffffffu, p[j], 2);\
    _Pragma("unroll")                                                         \
    for (int j = 0; j < 4; ++j) p[j] += __shfl_xor_sync(0xffffffffu, p[j], 1);\
    _Pragma("unroll")                                                         \
    for (int j = 0; j < 4; ++j) {                                             \
        bool valid = (E0) + j < end;                                          \
        if (!valid) p[j] = -CUDART_INF_F;                                     \
        sattr += valid ? __int_as_float((ED)[j].y) : 0.f;                     \
    }                                                                         \
    _Pragma("unroll")                                                         \
    for (int j = 0; j < 4; ++j) {                                             \
        float w = __expf(p[j]);        /* 0 for tail edges */                 \
        dn += w;                                                              \
        ull w2 = pack2(w);                                                    \
        ulonglong2 xl2 = *(ulonglong2*)&(XLV)[j];                             \
        acc0 = fma2v(w2, xl2.x, acc0);                                        \
        acc1 = fma2v(w2, xl2.y, acc1);                                        \
    }                                                                         \
} while (0)

    if (beg < end) {
        int2   edA[4], edB[4];
        float4 xlA[4], xlB[4];
        LOAD_GROUP(beg, edA, xlA);
        int e = beg;
        while (true) {
            LOAD_GROUP(e + 4, edB, xlB);    // prefetch (pad-safe, unclamped)
            PROC_GROUP(e, edA, xlA);
            e += 4;
            if (e >= end) break;
            LOAD_GROUP(e + 4, edA, xlA);
            PROC_GROUP(e, edB, xlB);
            e += 4;
            if (e >= end) break;
        }
    }
#undef LOAD_GROUP
#undef PROC_GROUP

    // self loop (always added, edge_attr = mean of incoming non-self attrs)
    {
        int   c  = end - beg;               // non-self incoming count
        float la = (c > 0) ? sattr / (float)c : 0.f;
        float4 xl4 = *(const float4*)&XL[n * HCC + base];
        ulonglong2 xl2 = *(ulonglong2*)&xl4;
        ull la2 = pack2(la);
        ull m0 = fma2v(la2, we2.x, add2(xl2.x, xr2.x));
        ull m1 = fma2v(la2, we2.y, add2(xl2.y, xr2.y));
        float2 ma = unpack2(m0), mb = unpack2(m1);
        float l0 = fmaxf(ma.x, 0.2f * ma.x);
        float l1 = fmaxf(ma.y, 0.2f * ma.y);
        float l2 = fmaxf(mb.x, 0.2f * mb.x);
        float l3 = fmaxf(mb.y, 0.2f * mb.y);
        float p = fmaf(l3, at4.w, fmaf(l2, at4.z, fmaf(l1, at4.y, l0 * at4.x)));
        p += __shfl_xor_sync(0xffffffffu, p, 4);
        p += __shfl_xor_sync(0xffffffffu, p, 2);
        p += __shfl_xor_sync(0xffffffffu, p, 1);
        float w = __expf(p);
        dn += w;
        ull w2 = pack2(w);
        acc0 = fma2v(w2, xl2.x, acc0);
        acc1 = fma2v(w2, xl2.y, acc1);
    }

    float4 b4 = *(const float4*)&bias[base];
    float inv = 1.f / dn;
    float2 a01 = unpack2(acc0);
    float2 a23 = unpack2(acc1);
    float4 o;
    o.x = fmaf(a01.x, inv, b4.x);
    o.y = fmaf(a01.y, inv, b4.y);
    o.z = fmaf(a23.x, inv, b4.z);
    o.w = fmaf(a23.y, inv, b4.w);
    if (applyElu) {
        o.x = (o.x > 0.f) ? o.x : (__expf(o.x) - 1.f);
        o.y = (o.y > 0.f) ? o.y : (__expf(o.y) - 1.f);
        o.z = (o.z > 0.f) ? o.z : (__expf(o.z) - 1.f);
        o.w = (o.w > 0.f) ? o.w : (__expf(o.w) - 1.f);
    }
    *(float4*)&out[n * HCC + base] = o;
}

// ---------------- launch ----------------------------------------------------
extern "C" void kernel_launch(void* const* d_in, const int* in_sizes, int n_in,
                              void* d_out, int out_size) {
    const float* x     = (const float*)d_in[0];
    const int*   ei    = (const int*)d_in[1];
    const float* eattr = (const float*)d_in[2];
    const float* Wl1 = (const float*)d_in[3];
    const float* bl1 = (const float*)d_in[4];
    const float* Wr1 = (const float*)d_in[5];
    const float* br1 = (const float*)d_in[6];
    const float* We1 = (const float*)d_in[7];
    const float* att1= (const float*)d_in[8];
    const float* b1  = (const float*)d_in[9];
    const float* Wl2 = (const float*)d_in[10];
    const float* bl2 = (const float*)d_in[11];
    const float* Wr2 = (const float*)d_in[12];
    const float* br2 = (const float*)d_in[13];
    const float* We2 = (const float*)d_in[14];
    const float* att2= (const float*)d_in[15];
    const float* b2  = (const float*)d_in[16];
    const float* Wo  = (const float*)d_in[17];
    const float* bo  = (const float*)d_in[18];
    float* out = (float*)d_out;

    int E = in_sizes[1] / 2;        // 640000
    int N = in_sizes[0] / HCC;      // 20000

    float *XL, *XR, *H;
    cudaGetSymbolAddress((void**)&XL, g_XL);
    cudaGetSymbolAddress((void**)&XR, g_XR);
    cudaGetSymbolAddress((void**)&H,  g_H);

    // secondary stream + events for CSR || GEMM1 overlap
    static cudaStream_t s1 = nullptr;
    static cudaEvent_t evFork = nullptr, evJoin = nullptr;
    if (s1 == nullptr) {
        cudaStreamCreateWithFlags(&s1, cudaStreamNonBlocking);
        cudaEventCreateWithFlags(&evFork, cudaEventDisableTiming);
        cudaEventCreateWithFlags(&evJoin, cudaEventDisableTiming);
    }

    dim3 gemmGrid((N + 63) / 64, HCC / 64);
    dim3 gemmGridOut((N + 63) / 64, DOUT / 64);
    int edgeBlocks = (N * 32 + 255) / 256;       // one warp per node
    int eBlocks4   = ((E + 3) / 4 + 255) / 256;  // 4 edges per thread
    int nBlocks    = (N + 255) / 256;

    // ---- fork: CSR build on s1, layer-1 GEMM on main stream
    cudaEventRecord(evFork, 0);
    cudaStreamWaitEvent(s1, evFork, 0);

    zero_counts_kernel<<<nBlocks, 256, 0, s1>>>();
    hist_kernel<<<eBlocks4, 256, 0, s1>>>(ei, E);
    scan_kernel<<<1, 1024, 0, s1>>>(N);
    scatter_kernel<<<eBlocks4, 256, 0, s1>>>(ei, eattr, E);
    cudaEventRecord(evJoin, s1);

    sgemm_dual_bias<<<gemmGrid, 256>>>(x, Wl1, Wr1, bl1, br1, XL, XR, N, HCC, HCC);

    cudaStreamWaitEvent(0, evJoin, 0);

    // layer 1 edge phase
    gat_edge_kernel<<<edgeBlocks, 256>>>(XL, XR, att1, We1, b1, H, 1);

    // layer 2
    sgemm_dual_bias<<<gemmGrid, 256>>>(H, Wl2, Wr2, bl2, br2, XL, XR, N, HCC, HCC);
    gat_edge_kernel<<<edgeBlocks, 256>>>(XL, XR, att2, We2, b2, H, 1);

    // output projection
    sgemm_bias<<<gemmGridOut, 256>>>(H, Wo, bo, out, N, DOUT, HCC);
}

// round 17
// speedup vs baseline: 1.4394x; 1.0089x over previous
#include <cuda_runtime.h>
#include <math_constants.h>

// Problem constants (fixed by the dataset)
#define NN   20000      // nodes
#define EE   640000     // edges
#define HCC  128        // H * C
#define NH   4          // heads
#define CH   32         // channels per head
#define DOUT 64

// ---------------- device scratch (static: no allocations allowed) -----------
__device__ float g_XL[NN * HCC];
__device__ float g_XR[NN * HCC];
__device__ float g_H [NN * HCC];
__device__ int   g_cnt[NN];
__device__ int   g_cur[NN];
__device__ int   g_rowptr[NN + 1];
__device__ int2  g_ecsr[EE + 16];   // non-self edges, CSR by dst; zero-init pad
                                    // (lets the edge kernel prefetch unclamped)

// ---------------- packed fp32x2 helpers (Blackwell, compile-proven) ---------
typedef unsigned long long ull;
__device__ __forceinline__ void ffma2(ull& d, ull a, ull b) {
    asm("fma.rn.f32x2 %0, %1, %2, %0;" : "+l"(d) : "l"(a), "l"(b));
}
__device__ __forceinline__ ull fma2v(ull a, ull b, ull c) {
    ull d;
    asm("fma.rn.f32x2 %0, %1, %2, %3;" : "=l"(d) : "l"(a), "l"(b), "l"(c));
    return d;
}
__device__ __forceinline__ ull add2(ull a, ull b) {
    ull d;
    asm("add.rn.f32x2 %0, %1, %2;" : "=l"(d) : "l"(a), "l"(b));
    return d;
}
__device__ __forceinline__ ull pack2(float x) {
    ull r;
    asm("mov.b64 %0, {%1, %1};" : "=l"(r) : "f"(x));
    return r;
}
__device__ __forceinline__ float2 unpack2(ull v) {
    float2 o;
    asm("mov.b64 {%0, %1}, %2;" : "=f"(o.x), "=f"(o.y) : "l"(v));
    return o;
}

// ---------------- CSR build (self-edges filtered out here) ------------------
__global__ void zero_counts_kernel() {
    int i = blockIdx.x * blockDim.x + threadIdx.x;
    if (i < NN) { g_cnt[i] = 0; g_cur[i] = 0; }
}

// histogram (non-self only); single atomic per edge; 4-batched loads for MLP
__global__ void hist_kernel(const int* __restrict__ ei, int E) {
    int T = gridDim.x * blockDim.x;
    int t = blockIdx.x * blockDim.x + threadIdx.x;
    int s[4], d[4];
    bool v[4];
    #pragma unroll
    for (int j = 0; j < 4; ++j) {
        int e = t + j * T;
        v[j] = (e < E);
        int ec = v[j] ? e : 0;
        s[j] = ei[ec];
        d[j] = ei[E + ec];
    }
    #pragma unroll
    for (int j = 0; j < 4; ++j) {
        if (!v[j] || d[j] < 0 || d[j] >= NN || s[j] == d[j]) continue;
        atomicAdd(&g_cnt[d[j]], 1);
    }
}

// single-block exclusive scan of g_cnt -> g_rowptr
__global__ void scan_kernel(int n) {
    __shared__ int sums[1024];
    int tid = threadIdx.x;
    int per = (n + 1023) >> 10;
    int beg = tid * per;
    int end = beg + per;
    if (beg > n) beg = n;
    if (end > n) end = n;
    int s = 0;
    for (int i = beg; i < end; ++i) s += g_cnt[i];
    sums[tid] = s;
    __syncthreads();
    for (int off = 1; off < 1024; off <<= 1) {
        int v = (tid >= off) ? sums[tid - off] : 0;
        __syncthreads();
        sums[tid] += v;
        __syncthreads();
    }
    int run = (tid == 0) ? 0 : sums[tid - 1];
    for (int i = beg; i < end; ++i) { g_rowptr[i] = run; run += g_cnt[i]; }
    if (tid == 0) g_rowptr[n] = sums[1023];
}

// scatter (non-self only); 4-batched loads
__global__ void scatter_kernel(const int* __restrict__ ei,
                               const float* __restrict__ eattr, int E) {
    int T = gridDim.x * blockDim.x;
    int t = blockIdx.x * blockDim.x + threadIdx.x;
    int   s[4], d[4];
    float a[4];
    bool  v[4];
    #pragma unroll
    for (int j = 0; j < 4; ++j) {
        int e = t + j * T;
        v[j] = (e < E);
        int ec = v[j] ? e : 0;
        s[j] = ei[ec];
        d[j] = ei[E + ec];
        a[j] = eattr[ec];
    }
    #pragma unroll
    for (int j = 0; j < 4; ++j) {
        if (!v[j] || d[j] < 0 || d[j] >= NN || s[j] == d[j]) continue;
        int pos = g_rowptr[d[j]] + atomicAdd(&g_cur[d[j]], 1);
        g_ecsr[pos] = make_int2(s[j], __float_as_int(a[j]));
    }
}

// ---------------- fused dual SGEMM (FFMA2 inner, known good) ----------------
__global__ __launch_bounds__(256)
void sgemm_dual_bias(const float* __restrict__ A,
                     const float* __restrict__ Bl, const float* __restrict__ Br,
                     const float* __restrict__ bl, const float* __restrict__ br,
                     float* __restrict__ CL, float* __restrict__ CR,
                     int M, int N, int K) {
    __shared__ float As [16][64];
    __shared__ float Bls[16][64];
    __shared__ float Brs[16][64];
    int tid = threadIdx.x;
    int tx = tid & 15, ty = tid >> 4;
    int bm = blockIdx.x, bn = blockIdx.y;
    int rowBase = bm * 64;

    int aRow = tid >> 2;
    int aK   = (tid & 3) * 4;
    int bK   = tid >> 4;
    int bN   = (tid & 15) * 4;

    ull accL[4][2] = {};
    ull accR[4][2] = {};

    for (int k0 = 0; k0 < K; k0 += 16) {
        float4 av;
        int gr = rowBase + aRow;
        if (gr < M) av = *(const float4*)&A[(long)gr * K + k0 + aK];
        else        av = make_float4(0.f, 0.f, 0.f, 0.f);
        As[aK + 0][aRow] = av.x;
        As[aK + 1][aRow] = av.y;
        As[aK + 2][aRow] = av.z;
        As[aK + 3][aRow] = av.w;
        long boff = (long)(k0 + bK) * N + bn * 64 + bN;
        *(float4*)&Bls[bK][bN] = *(const float4*)&Bl[boff];
        *(float4*)&Brs[bK][bN] = *(const float4*)&Br[boff];
        __syncthreads();
        #pragma unroll
        for (int kk = 0; kk < 16; ++kk) {
            float4 a4 = *(const float4*)&As[kk][ty * 4];
            ulonglong2 blp = *(const ulonglong2*)&Bls[kk][tx * 4];
            ulonglong2 brp = *(const ulonglong2*)&Brs[kk][tx * 4];
            ull ap[4];
            ap[0] = pack2(a4.x); ap[1] = pack2(a4.y);
            ap[2] = pack2(a4.z); ap[3] = pack2(a4.w);
            #pragma unroll
            for (int i = 0; i < 4; ++i) {
                ffma2(accL[i][0], ap[i], blp.x);
                ffma2(accL[i][1], ap[i], blp.y);
                ffma2(accR[i][0], ap[i], brp.x);
                ffma2(accR[i][1], ap[i], brp.y);
            }
        }
        __syncthreads();
    }
    float4 bl4 = *(const float4*)&bl[bn * 64 + tx * 4];
    float4 br4 = *(const float4*)&br[bn * 64 + tx * 4];
    #pragma unroll
    for (int i = 0; i < 4; ++i) {
        int gr = rowBase + ty * 4 + i;
        if (gr < M) {
            float2 l0 = unpack2(accL[i][0]);
            float2 l1 = unpack2(accL[i][1]);
            float2 r0 = unpack2(accR[i][0]);
            float2 r1 = unpack2(accR[i][1]);
            float4 ol, orr;
            ol.x  = l0.x + bl4.x; ol.y  = l0.y + bl4.y;
            ol.z  = l1.x + bl4.z; ol.w  = l1.y + bl4.w;
            orr.x = r0.x + br4.x; orr.y = r0.y + br4.y;
            orr.z = r1.x + br4.z; orr.w = r1.y + br4.w;
            long coff = (long)gr * N + bn * 64 + tx * 4;
            *(float4*)&CL[coff] = ol;
            *(float4*)&CR[coff] = orr;
        }
    }
}

// ---------------- single SGEMM (output projection), FFMA2 inner -------------
__global__ __launch_bounds__(256)
void sgemm_bias(const float* __restrict__ A, const float* __restrict__ B,
                const float* __restrict__ bias, float* __restrict__ C,
                int M, int N, int K) {
    __shared__ float As[16][64];
    __shared__ float Bs[16][64];
    int tid = threadIdx.x;
    int tx = tid & 15, ty = tid >> 4;
    int bm = blockIdx.x, bn = blockIdx.y;
    int rowBase = bm * 64;

    int aRow = tid >> 2;
    int aK   = (tid & 3) * 4;
    int bK   = tid >> 4;
    int bN   = (tid & 15) * 4;

    ull acc[4][2] = {};
    for (int k0 = 0; k0 < K; k0 += 16) {
        float4 av;
        int gr = rowBase + aRow;
        if (gr < M) av = *(const float4*)&A[(long)gr * K + k0 + aK];
        else        av = make_float4(0.f, 0.f, 0.f, 0.f);
        As[aK + 0][aRow] = av.x;
        As[aK + 1][aRow] = av.y;
        As[aK + 2][aRow] = av.z;
        As[aK + 3][aRow] = av.w;
        *(float4*)&Bs[bK][bN] = *(const float4*)&B[(long)(k0 + bK) * N + bn * 64 + bN];
        __syncthreads();
        #pragma unroll
        for (int kk = 0; kk < 16; ++kk) {
            float4 a4 = *(const float4*)&As[kk][ty * 4];
            ulonglong2 bp = *(const ulonglong2*)&Bs[kk][tx * 4];
            ull ap[4];
            ap[0] = pack2(a4.x); ap[1] = pack2(a4.y);
            ap[2] = pack2(a4.z); ap[3] = pack2(a4.w);
            #pragma unroll
            for (int i = 0; i < 4; ++i) {
                ffma2(acc[i][0], ap[i], bp.x);
                ffma2(acc[i][1], ap[i], bp.y);
            }
        }
        __syncthreads();
    }
    float4 bias4 = *(const float4*)&bias[bn * 64 + tx * 4];
    #pragma unroll
    for (int i = 0; i < 4; ++i) {
        int gr = rowBase + ty * 4 + i;
        if (gr < M) {
            float2 c0 = unpack2(acc[i][0]);
            float2 c1 = unpack2(acc[i][1]);
            float4 o;
            o.x = c0.x + bias4.x;
            o.y = c0.y + bias4.y;
            o.z = c1.x + bias4.z;
            o.w = c1.y + bias4.w;
            *(float4*)&C[(long)gr * N + bn * 64 + tx * 4] = o;
        }
    }
}

// ---------------- GATv2 edge phase: one warp per dst node ------------------
// 2 edge-slots x 16 lanes: each half-warp owns one edge; lane covers 8
// channels (2 x float4) of one head (4 lanes/head). Per edge: 1 shared shuffle
// round-pair, 0.5 expf/lane. No-max softmax (range-safe). Cross-slot merge
// (dn/sattr/acc via xor 16) once per node. Self-loop after merge.
__global__ __launch_bounds__(256)
void gat_edge_kernel(const float* __restrict__ XL, const float* __restrict__ XR,
                     const float* __restrict__ att, const float* __restrict__ We,
                     const float* __restrict__ bias, float* __restrict__ out,
                     int applyElu) {
    int gid  = blockIdx.x * blockDim.x + threadIdx.x;
    int n    = gid >> 5;
    int lane = gid & 31;
    if (n >= NN) return;

    int slot = lane >> 4;               // 0 or 1: which edge of the pair
    int l16  = lane & 15;
    int base = (l16 >> 2) * CH + (l16 & 3) * 8;   // head*32 + quad*8

    float4 xrA = *(const float4*)&XR[n * HCC + base];
    float4 xrB = *(const float4*)&XR[n * HCC + base + 4];
    float4 atA = *(const float4*)&att[base];
    float4 atB = *(const float4*)&att[base + 4];
    float4 weA = *(const float4*)&We[base];
    float4 weB = *(const float4*)&We[base + 4];
    ulonglong2 xrA2 = *(ulonglong2*)&xrA;
    ulonglong2 xrB2 = *(ulonglong2*)&xrB;
    ulonglong2 weA2 = *(ulonglong2*)&weA;
    ulonglong2 weB2 = *(ulonglong2*)&weB;

    float dn = 0.f, sattr = 0.f;
    ull acc[4] = {0, 0, 0, 0};          // 8 channels packed

    int beg = g_rowptr[n], end = g_rowptr[n + 1];

#define LOAD2(E, ED, XA, XB) do {                                             \
    (ED) = g_ecsr[(E) + slot];                                                \
    long off = (long)(ED).x * HCC + base;                                     \
    (XA) = *(const float4*)&XL[off];                                          \
    (XB) = *(const float4*)&XL[off + 4];                                      \
} while (0)

#define PROC2(E, ED, XA, XB) do {                                             \
    ulonglong2 xa2 = *(ulonglong2*)&(XA);                                     \
    ulonglong2 xb2 = *(ulonglong2*)&(XB);                                     \
    ull ae2 = pack2(__int_as_float((ED).y));                                  \
    ull m0 = fma2v(ae2, weA2.x, add2(xa2.x, xrA2.x));                         \
    ull m1 = fma2v(ae2, weA2.y, add2(xa2.y, xrA2.y));                         \
    ull m2 = fma2v(ae2, weB2.x, add2(xb2.x, xrB2.x));                         \
    ull m3 = fma2v(ae2, weB2.y, add2(xb2.y, xrB2.y));                         \
    float2 f0 = unpack2(m0), f1 = unpack2(m1);                                \
    float2 f2 = unpack2(m2), f3 = unpack2(m3);                                \
    float p = fmaxf(f0.x, 0.2f * f0.x) * atA.x;                               \
    p = fmaf(fmaxf(f0.y, 0.2f * f0.y), atA.y, p);                             \
    p = fmaf(fmaxf(f1.x, 0.2f * f1.x), atA.z, p);                             \
    p = fmaf(fmaxf(f1.y, 0.2f * f1.y), atA.w, p);                             \
    p = fmaf(fmaxf(f2.x, 0.2f * f2.x), atB.x, p);                             \
    p = fmaf(fmaxf(f2.y, 0.2f * f2.y), atB.y, p);                             \
    p = fmaf(fmaxf(f3.x, 0.2f * f3.x), atB.z, p);                             \
    p = fmaf(fmaxf(f3.y, 0.2f * f3.y), atB.w, p);                             \
    p += __shfl_xor_sync(0xffffffffu, p, 1);                                  \
    p += __shfl_xor_sync(0xffffffffu, p, 2);                                  \
    bool valid = (E) + slot < end;                                            \
    if (!valid) p = -CUDART_INF_F;                                            \
    sattr += valid ? __int_as_float((ED).y) : 0.f;                            \
    float w = __expf(p);               /* 0 for invalid slot */               \
    dn += w;                                                                  \
    ull w2 = pack2(w);                                                        \
    acc[0] = fma2v(w2, xa2.x, acc[0]);                                        \
    acc[1] = fma2v(w2, xa2.y, acc[1]);                                        \
    acc[2] = fma2v(w2, xb2.x, acc[2]);                                        \
    acc[3] = fma2v(w2, xb2.y, acc[3]);                                        \
} while (0)

    if (beg < end) {
        int2 edA, edB;
        float4 xaA, xbA, xaB, xbB;
        LOAD2(beg, edA, xaA, xbA);
        int e = beg;
        while (true) {
            LOAD2(e + 2, edB, xaB, xbB);    // prefetch (pad-safe, unclamped)
            PROC2(e, edA, xaA, xbA);
            e += 2;
            if (e >= end) break;
            LOAD2(e + 2, edA, xaA, xbA);
            PROC2(e, edB, xaB, xbB);
            e += 2;
            if (e >= end) break;
        }
    }
#undef LOAD2
#undef PROC2

    // merge the two edge-slots (channel mapping identical across slots)
    dn    += __shfl_xor_sync(0xffffffffu, dn, 16);
    sattr += __shfl_xor_sync(0xffffffffu, sattr, 16);
    #pragma unroll
    for (int i = 0; i < 4; ++i)
        acc[i] = add2(acc[i], __shfl_xor_sync(0xffffffffu, acc[i], 16));

    // self loop (always added, edge_attr = mean of incoming non-self attrs)
    {
        int   c  = end - beg;
        float la = (c > 0) ? sattr / (float)c : 0.f;
        long off = (long)n * HCC + base;
        float4 xa = *(const float4*)&XL[off];
        float4 xb = *(const float4*)&XL[off + 4];
        ulonglong2 xa2 = *(ulonglong2*)&xa;
        ulonglong2 xb2 = *(ulonglong2*)&xb;
        ull la2 = pack2(la);
        ull m0 = fma2v(la2, weA2.x, add2(xa2.x, xrA2.x));
        ull m1 = fma2v(la2, weA2.y, add2(xa2.y, xrA2.y));
        ull m2 = fma2v(la2, weB2.x, add2(xb2.x, xrB2.x));
        ull m3 = fma2v(la2, weB2.y, add2(xb2.y, xrB2.y));
        float2 f0 = unpack2(m0), f1 = unpack2(m1);
        float2 f2 = unpack2(m2), f3 = unpack2(m3);
        float p = fmaxf(f0.x, 0.2f * f0.x) * atA.x;
        p = fmaf(fmaxf(f0.y, 0.2f * f0.y), atA.y, p);
        p = fmaf(fmaxf(f1.x, 0.2f * f1.x), atA.z, p);
        p = fmaf(fmaxf(f1.y, 0.2f * f1.y), atA.w, p);
        p = fmaf(fmaxf(f2.x, 0.2f * f2.x), atB.x, p);
        p = fmaf(fmaxf(f2.y, 0.2f * f2.y), atB.y, p);
        p = fmaf(fmaxf(f3.x, 0.2f * f3.x), atB.z, p);
        p = fmaf(fmaxf(f3.y, 0.2f * f3.y), atB.w, p);
        p += __shfl_xor_sync(0xffffffffu, p, 1);
        p += __shfl_xor_sync(0xffffffffu, p, 2);
        float w = __expf(p);
        dn += w;
        ull w2 = pack2(w);
        acc[0] = fma2v(w2, xa2.x, acc[0]);
        acc[1] = fma2v(w2, xa2.y, acc[1]);
        acc[2] = fma2v(w2, xb2.x, acc[2]);
        acc[3] = fma2v(w2, xb2.y, acc[3]);
    }

    if (slot == 0) {
        float inv = 1.f / dn;
        float4 bA = *(const float4*)&bias[base];
        float4 bB = *(const float4*)&bias[base + 4];
        float2 a0 = unpack2(acc[0]);
        float2 a1 = unpack2(acc[1]);
        float2 a2 = unpack2(acc[2]);
        float2 a3 = unpack2(acc[3]);
        float4 oA, oB;
        oA.x = fmaf(a0.x, inv, bA.x);
        oA.y = fmaf(a0.y, inv, bA.y);
        oA.z = fmaf(a1.x, inv, bA.z);
        oA.w = fmaf(a1.y, inv, bA.w);
        oB.x = fmaf(a2.x, inv, bB.x);
        oB.y = fmaf(a2.y, inv, bB.y);
        oB.z = fmaf(a3.x, inv, bB.z);
        oB.w = fmaf(a3.y, inv, bB.w);
        if (applyElu) {
            oA.x = (oA.x > 0.f) ? oA.x : (__expf(oA.x) - 1.f);
            oA.y = (oA.y > 0.f) ? oA.y : (__expf(oA.y) - 1.f);
            oA.z = (oA.z > 0.f) ? oA.z : (__expf(oA.z) - 1.f);
            oA.w = (oA.w > 0.f) ? oA.w : (__expf(oA.w) - 1.f);
            oB.x = (oB.x > 0.f) ? oB.x : (__expf(oB.x) - 1.f);
            oB.y = (oB.y > 0.f) ? oB.y : (__expf(oB.y) - 1.f);
            oB.z = (oB.z > 0.f) ? oB.z : (__expf(oB.z) - 1.f);
            oB.w = (oB.w > 0.f) ? oB.w : (__expf(oB.w) - 1.f);
        }
        long ooff = (long)n * HCC + base;
        *(float4*)&out[ooff]     = oA;
        *(float4*)&out[ooff + 4] = oB;
    }
}

// ---------------- launch ----------------------------------------------------
extern "C" void kernel_launch(void* const* d_in, const int* in_sizes, int n_in,
                              void* d_out, int out_size) {
    const float* x     = (const float*)d_in[0];
    const int*   ei    = (const int*)d_in[1];
    const float* eattr = (const float*)d_in[2];
    const float* Wl1 = (const float*)d_in[3];
    const float* bl1 = (const float*)d_in[4];
    const float* Wr1 = (const float*)d_in[5];
    const float* br1 = (const float*)d_in[6];
    const float* We1 = (const float*)d_in[7];
    const float* att1= (const float*)d_in[8];
    const float* b1  = (const float*)d_in[9];
    const float* Wl2 = (const float*)d_in[10];
    const float* bl2 = (const float*)d_in[11];
    const float* Wr2 = (const float*)d_in[12];
    const float* br2 = (const float*)d_in[13];
    const float* We2 = (const float*)d_in[14];
    const float* att2= (const float*)d_in[15];
    const float* b2  = (const float*)d_in[16];
    const float* Wo  = (const float*)d_in[17];
    const float* bo  = (const float*)d_in[18];
    float* out = (float*)d_out;

    int E = in_sizes[1] / 2;        // 640000
    int N = in_sizes[0] / HCC;      // 20000

    float *XL, *XR, *H;
    cudaGetSymbolAddress((void**)&XL, g_XL);
    cudaGetSymbolAddress((void**)&XR, g_XR);
    cudaGetSymbolAddress((void**)&H,  g_H);

    // secondary stream + events for CSR || GEMM1 overlap
    static cudaStream_t s1 = nullptr;
    static cudaEvent_t evFork = nullptr, evJoin = nullptr;
    if (s1 == nullptr) {
        cudaStreamCreateWithFlags(&s1, cudaStreamNonBlocking);
        cudaEventCreateWithFlags(&evFork, cudaEventDisableTiming);
        cudaEventCreateWithFlags(&evJoin, cudaEventDisableTiming);
    }

    dim3 gemmGrid((N + 63) / 64, HCC / 64);
    dim3 gemmGridOut((N + 63) / 64, DOUT / 64);
    int edgeBlocks = (N * 32 + 255) / 256;       // one warp per node
    int eBlocks4   = ((E + 3) / 4 + 255) / 256;  // 4 edges per thread
    int nBlocks    = (N + 255) / 256;

    // ---- fork: CSR build on s1, layer-1 GEMM on main stream
    cudaEventRecord(evFork, 0);
    cudaStreamWaitEvent(s1, evFork, 0);

    zero_counts_kernel<<<nBlocks, 256, 0, s1>>>();
    hist_kernel<<<eBlocks4, 256, 0, s1>>>(ei, E);
    scan_kernel<<<1, 1024, 0, s1>>>(N);
    scatter_kernel<<<eBlocks4, 256, 0, s1>>>(ei, eattr, E);
    cudaEventRecord(evJoin, s1);

    sgemm_dual_bias<<<gemmGrid, 256>>>(x, Wl1, Wr1, bl1, br1, XL, XR, N, HCC, HCC);

    cudaStreamWaitEvent(0, evJoin, 0);

    // layer 1 edge phase
    gat_edge_kernel<<<edgeBlocks, 256>>>(XL, XR, att1, We1, b1, H, 1);

    // layer 2
    sgemm_dual_bias<<<gemmGrid, 256>>>(H, Wl2, Wr2, bl2, br2, XL, XR, N, HCC, HCC);
    gat_edge_kernel<<<edgeBlocks, 256>>>(XL, XR, att2, We2, b2, H, 1);

    // output projection
    sgemm_bias<<<gemmGridOut, 256>>>(H, Wo, bo, out, N, DOUT, HCC);
}